// round 11
// baseline (speedup 1.0000x reference)
#include <cuda_runtime.h>
#include <cuda_bf16.h>
#include <math.h>
#include <stdint.h>

// Problem constants
#define Bb   2
#define Ll   1024
#define Tt   2048        // Bb*Ll tokens
#define DIN  512
#define DM   1024
#define NLr  4
#define EE   2048
#define NN   16
#define RR   64
#define XSK  8           // split-K factor for xproj

// ---------------- scratch (device globals; no runtime allocation) ----------
__device__ float g_h   [Tt * DM];
__device__ float g_hn  [Tt * DM];
__device__ float g_xz  [Tt * 2 * EE];
__device__ float g_xm  [Tt * EE];
__device__ float g_xdbl[Tt * 96];
__device__ float g_dt  [Tt * EE];
__device__ float g_A   [NLr * EE * NN];
__device__ float g_xr  [Tt * DIN];                 // tf32-rounded x
__device__ float g_xpart[XSK * Tt * 96];           // xproj split-K partials
// tf32-rounded weights
__device__ float g_wip     [DM * DIN];
__device__ float g_winproj [NLr * 2 * EE * DM];
__device__ float g_wxproj  [NLr * 96 * EE];
__device__ float g_wop     [DIN * DM];
// bf16 hi/lo split (outproj path probe)
__device__ __nv_bfloat16 g_wout_hi[NLr * DM * EE];
__device__ __nv_bfloat16 g_wout_lo[NLr * DM * EE];
__device__ __nv_bfloat16 g_y_hi[Tt * EE];
__device__ __nv_bfloat16 g_y_lo[Tt * EE];

// ---------------------------------------------------------------------------
// helpers
// ---------------------------------------------------------------------------
__device__ __forceinline__ uint32_t f2tf(float x) {
    uint32_t r;
    asm("cvt.rna.tf32.f32 %0, %1;" : "=r"(r) : "f"(x));
    return r;
}
__device__ __forceinline__ float rtf(float x) { return __uint_as_float(f2tf(x)); }

__device__ __forceinline__ void mma8(float& d0, float& d1, float& d2, float& d3,
                                     uint32_t a0, uint32_t a1, uint32_t a2, uint32_t a3,
                                     uint32_t b0, uint32_t b1) {
    asm volatile(
        "mma.sync.aligned.m16n8k8.row.col.f32.tf32.tf32.f32 "
        "{%0,%1,%2,%3}, {%4,%5,%6,%7}, {%8,%9}, {%0,%1,%2,%3};"
        : "+f"(d0), "+f"(d1), "+f"(d2), "+f"(d3)
        : "r"(a0), "r"(a1), "r"(a2), "r"(a3), "r"(b0), "r"(b1));
}
__device__ __forceinline__ void mma16bf(float& d0, float& d1, float& d2, float& d3,
                                        uint32_t a0, uint32_t a1, uint32_t a2, uint32_t a3,
                                        uint32_t b0, uint32_t b1) {
    asm volatile(
        "mma.sync.aligned.m16n8k16.row.col.f32.bf16.bf16.f32 "
        "{%0,%1,%2,%3}, {%4,%5,%6,%7}, {%8,%9}, {%0,%1,%2,%3};"
        : "+f"(d0), "+f"(d1), "+f"(d2), "+f"(d3)
        : "r"(a0), "r"(a1), "r"(a2), "r"(a3), "r"(b0), "r"(b1));
}
__device__ __forceinline__ void ldsm4(uint32_t* r, uint32_t a) {
    asm volatile("ldmatrix.sync.aligned.m8n8.x4.shared.b16 {%0,%1,%2,%3}, [%4];"
                 : "=r"(r[0]), "=r"(r[1]), "=r"(r[2]), "=r"(r[3]) : "r"(a));
}
__device__ __forceinline__ void ldsm2(uint32_t* r, uint32_t a) {
    asm volatile("ldmatrix.sync.aligned.m8n8.x2.shared.b16 {%0,%1}, [%2];"
                 : "=r"(r[0]), "=r"(r[1]) : "r"(a));
}
__device__ __forceinline__ void cp16(void* dst, const void* src) {
    uint32_t d = (uint32_t)__cvta_generic_to_shared(dst);
    asm volatile("cp.async.cg.shared.global [%0], [%1], 16;" :: "r"(d), "l"(src));
}
__device__ __forceinline__ void cp16s(uint32_t dst, const void* src) {
    asm volatile("cp.async.cg.shared.global [%0], [%1], 16;" :: "r"(dst), "l"(src));
}
__device__ __forceinline__ void cp4(void* dst, const void* src) {
    uint32_t d = (uint32_t)__cvta_generic_to_shared(dst);
    asm volatile("cp.async.ca.shared.global [%0], [%1], 4;" :: "r"(d), "l"(src));
}
__device__ __forceinline__ void cpcommit() { asm volatile("cp.async.commit_group;"); }
template<int NG> __device__ __forceinline__ void cpwait() {
    asm volatile("cp.async.wait_group %0;" :: "n"(NG));
}

// ---------------------------------------------------------------------------
// Fused prep: tf32-round x/ip/inproj/xproj/op; bf16 hi/lo split of outproj;
// A transform. One launch.
// ---------------------------------------------------------------------------
#define P_S0 ((size_t)(Tt * DIN / 4))                       // x
#define P_S1 (P_S0 + (size_t)(DM * DIN / 4))                // ip_w
#define P_S2 (P_S1 + (size_t)(NLr * 2 * EE * DM / 4))       // inproj_w
#define P_S3 (P_S2 + (size_t)(NLr * 96 * EE / 4))           // xproj_w
#define P_S4 (P_S3 + (size_t)(NLr * DM * EE / 4))           // outproj_w (bf16 split)
#define P_S5 (P_S4 + (size_t)(DIN * DM / 4))                // op_w
#define P_TOT (P_S5 + (size_t)(NLr * EE * NN))              // + A elems

__global__ void prep_all(const float4* __restrict__ x,   const float4* __restrict__ ipw,
                         const float4* __restrict__ inw, const float4* __restrict__ xpw,
                         const float4* __restrict__ otw, const float4* __restrict__ opw,
                         const float* __restrict__ A_log)
{
    const size_t i = (size_t)blockIdx.x * 256 + threadIdx.x;
    if (i < P_S3) {
        const float4* s; float4* d; size_t j;
        if      (i < P_S0) { s = x;   d = (float4*)g_xr;      j = i; }
        else if (i < P_S1) { s = ipw; d = (float4*)g_wip;     j = i - P_S0; }
        else if (i < P_S2) { s = inw; d = (float4*)g_winproj; j = i - P_S1; }
        else               { s = xpw; d = (float4*)g_wxproj;  j = i - P_S2; }
        float4 v = s[j];
        v.x = rtf(v.x); v.y = rtf(v.y); v.z = rtf(v.z); v.w = rtf(v.w);
        d[j] = v;
    } else if (i < P_S4) {
        const size_t j = i - P_S3;
        const float4 v = otw[j];
        __nv_bfloat16 h0 = __float2bfloat16(v.x), h1 = __float2bfloat16(v.y);
        __nv_bfloat16 h2 = __float2bfloat16(v.z), h3 = __float2bfloat16(v.w);
        __nv_bfloat16 l0 = __float2bfloat16(v.x - __bfloat162float(h0));
        __nv_bfloat16 l1 = __float2bfloat16(v.y - __bfloat162float(h1));
        __nv_bfloat16 l2 = __float2bfloat16(v.z - __bfloat162float(h2));
        __nv_bfloat16 l3 = __float2bfloat16(v.w - __bfloat162float(h3));
        __nv_bfloat162* H = (__nv_bfloat162*)g_wout_hi;
        __nv_bfloat162* L = (__nv_bfloat162*)g_wout_lo;
        H[j * 2]     = __halves2bfloat162(h0, h1);
        H[j * 2 + 1] = __halves2bfloat162(h2, h3);
        L[j * 2]     = __halves2bfloat162(l0, l1);
        L[j * 2 + 1] = __halves2bfloat162(l2, l3);
    } else if (i < P_S5) {
        const size_t j = i - P_S4;
        float4 v = opw[j];
        v.x = rtf(v.x); v.y = rtf(v.y); v.z = rtf(v.z); v.w = rtf(v.w);
        ((float4*)g_wop)[j] = v;
    } else if (i < P_TOT) {
        const size_t j = i - P_S5;
        g_A[j] = -expf(A_log[j]);
    }
}

// ---------------------------------------------------------------------------
// TF32 HMMA GEMM (proven R5/R10 config): 3-stage cp.async + ldmatrix.
// ---------------------------------------------------------------------------
template<int WMW, int WNW, int BETA, int BIAS, int SK>
__global__ __launch_bounds__(WMW * WNW * 32, 2)
void tgemm(const float* __restrict__ A, const float* __restrict__ W,
           const float* __restrict__ bias, float* __restrict__ C,
           int M, int N, int K, int lda)
{
    constexpr int NT  = WMW * WNW * 32;
    constexpr int BM  = WMW * 64;
    constexpr int BN  = WNW * 32;
    constexpr int ST  = 3;
    constexpr int AW  = BM * 20;
    constexpr int BW  = BN * 20;
    constexpr int AIT = (BM * 4 + NT - 1) / NT;
    constexpr int BIT = (BN * 4 + NT - 1) / NT;

    extern __shared__ float dynsm[];

    if (SK) {
        A += (size_t)blockIdx.z * K;
        W += (size_t)blockIdx.z * K;
        C += (size_t)blockIdx.z * M * N;
    }

    const int tid  = threadIdx.x;
    const int bm   = blockIdx.y * BM;
    const int bn   = blockIdx.x * BN;
    const int wid  = tid >> 5;
    const int lane = tid & 31;
    const int wm   = wid % WMW;
    const int wn   = wid / WMW;
    const int l4   = lane >> 2;
    const int lr   = lane & 3;

    const float* Ag = A + (size_t)bm * lda;
    const float* Wg = W + (size_t)bn * lda;

    float acc[4][4][4];
#pragma unroll
    for (int i = 0; i < 4; i++)
#pragma unroll
        for (int j = 0; j < 4; j++)
#pragma unroll
            for (int k = 0; k < 4; k++) acc[i][j][k] = 0.f;

    auto load_stage = [&](int st, int kt) {
        float* As = dynsm + st * AW;
        float* Bs = dynsm + ST * AW + st * BW;
#pragma unroll
        for (int i = 0; i < AIT; i++) {
            const int f = tid + i * NT;
            if (f < BM * 4) {
                const int row = f >> 2, c = (f & 3) << 2;
                cp16(As + row * 20 + c, Ag + (size_t)row * lda + kt * 16 + c);
            }
        }
#pragma unroll
        for (int i = 0; i < BIT; i++) {
            const int f = tid + i * NT;
            if (f < BN * 4) {
                const int row = f >> 2, c = (f & 3) << 2;
                cp16(Bs + row * 20 + c, Wg + (size_t)row * lda + kt * 16 + c);
            }
        }
        cpcommit();
    };

    load_stage(0, 0);
    load_stage(1, 1);

    const int sub  = lane >> 3, tr = lane & 7;
    const int aoff = ((sub & 1) * 8 + tr) * 20 + (sub >> 1) * 4;
    const int l15  = lane & 15;
    const int boff = (l15 & 7) * 20 + (l15 >> 3) * 4;
    const uint32_t Au = (uint32_t)__cvta_generic_to_shared(dynsm);
    const uint32_t Bu = (uint32_t)__cvta_generic_to_shared(dynsm + ST * AW);

    const int nt = K >> 4;
    for (int kt = 0; kt < nt; kt++) {
        cpwait<1>();
        __syncthreads();
        if (kt + 2 < nt) load_stage((kt + 2) % ST, kt + 2);

        const int st = kt % ST;
        const uint32_t aB = Au + (uint32_t)(st * AW + wm * 64 * 20 + aoff) * 4;
        const uint32_t bB = Bu + (uint32_t)(st * BW + wn * 32 * 20 + boff) * 4;
#pragma unroll
        for (int ks = 0; ks < 2; ks++) {
            uint32_t af[4][4], bf[4][2];
#pragma unroll
            for (int mt = 0; mt < 4; mt++)
                ldsm4(af[mt], aB + (uint32_t)(mt * 16 * 20 + ks * 8) * 4);
#pragma unroll
            for (int ntt = 0; ntt < 4; ntt++)
                ldsm2(bf[ntt], bB + (uint32_t)(ntt * 8 * 20 + ks * 8) * 4);
#pragma unroll
            for (int mt = 0; mt < 4; mt++)
#pragma unroll
                for (int ntt = 0; ntt < 4; ntt++)
                    mma8(acc[mt][ntt][0], acc[mt][ntt][1], acc[mt][ntt][2], acc[mt][ntt][3],
                         af[mt][0], af[mt][1], af[mt][2], af[mt][3],
                         bf[ntt][0], bf[ntt][1]);
        }
    }

#pragma unroll
    for (int mt = 0; mt < 4; mt++) {
        const int r0 = bm + wm * 64 + mt * 16 + l4;
#pragma unroll
        for (int ntt = 0; ntt < 4; ntt++) {
            const int c0 = bn + wn * 32 + ntt * 8 + lr * 2;
            float* p0 = C + (size_t)r0 * N + c0;
            float* p1 = p0 + (size_t)8 * N;
            float v0 = acc[mt][ntt][0], v1 = acc[mt][ntt][1];
            float v2 = acc[mt][ntt][2], v3 = acc[mt][ntt][3];
            if (BIAS) {
                const float b0 = bias[c0], b1 = bias[c0 + 1];
                v0 += b0; v1 += b1; v2 += b0; v3 += b1;
            }
            if (BETA) {
                const float2 o0 = *(const float2*)p0;
                const float2 o1 = *(const float2*)p1;
                v0 += o0.x; v1 += o0.y; v2 += o1.x; v3 += o1.y;
            }
            *(float2*)p0 = make_float2(v0, v1);
            *(float2*)p1 = make_float2(v2, v3);
        }
    }
}

// ---------------------------------------------------------------------------
// Split-bf16 GEMM (probe): C[M,N] += (Ah+Al)[M,K] * (Wh+Wl)[N,K]^T
// via Ah*Wh + Al*Wh + Ah*Wl (bf16 m16n8k16, fp32 accum).
// BM=128, BN=128, BK=32; 256 threads (8 warps of 64x32); 2-stage cp.async.
// smem: per stage 4 halves x (128 rows x 80B) = 40960 B; 2 stages = 81920 B.
// ---------------------------------------------------------------------------
#define BG_HB 10240      // bytes per half-region (128 rows * 80B)
#define BG_SMEM (2 * 4 * BG_HB)

__global__ __launch_bounds__(256, 2)
void bgemm(const __nv_bfloat16* __restrict__ Ah, const __nv_bfloat16* __restrict__ Al,
           const __nv_bfloat16* __restrict__ Wh, const __nv_bfloat16* __restrict__ Wl,
           float* __restrict__ C, int M, int N, int K)
{
    extern __shared__ char bsm[];
    const int tid  = threadIdx.x;
    const int wid  = tid >> 5;
    const int lane = tid & 31;
    const int wm   = wid & 1;        // 2 warps in M
    const int wn   = wid >> 1;       // 4 warps in N
    const int l4   = lane >> 2;
    const int lr   = lane & 3;
    const int bm   = blockIdx.y * 128;
    const int bn   = blockIdx.x * 128;

    const __nv_bfloat16* Ahg = Ah + (size_t)bm * K;
    const __nv_bfloat16* Alg = Al + (size_t)bm * K;
    const __nv_bfloat16* Whg = Wh + (size_t)bn * K;
    const __nv_bfloat16* Wlg = Wl + (size_t)bn * K;

    float acc[4][4][4];
#pragma unroll
    for (int i = 0; i < 4; i++)
#pragma unroll
        for (int j = 0; j < 4; j++)
#pragma unroll
            for (int k = 0; k < 4; k++) acc[i][j][k] = 0.f;

    const uint32_t smb = (uint32_t)__cvta_generic_to_shared(bsm);

    auto load_stage = [&](int st, int kt) {
        const uint32_t base = smb + st * 4 * BG_HB;
#pragma unroll
        for (int i = 0; i < 8; i++) {
            const int f    = tid + i * 256;      // 0..2047
            const int half = f >> 9;             // 0=Ah 1=Al 2=Wh 3=Wl
            const int cc   = f & 511;
            const int row  = cc >> 2;            // 0..127
            const int c    = cc & 3;             // 16B chunk in 64B row
            const __nv_bfloat16* src;
            if      (half == 0) src = Ahg + (size_t)row * K + kt * 32 + c * 8;
            else if (half == 1) src = Alg + (size_t)row * K + kt * 32 + c * 8;
            else if (half == 2) src = Whg + (size_t)row * K + kt * 32 + c * 8;
            else                src = Wlg + (size_t)row * K + kt * 32 + c * 8;
            cp16s(base + half * BG_HB + row * 80 + c * 16, src);
        }
        cpcommit();
    };

    load_stage(0, 0);

    // ldmatrix lane offsets (bytes, within an operand region)
    const uint32_t aoff = (uint32_t)(((lane & 7) + ((lane >> 3) & 1) * 8) * 80 +
                                     (lane >> 4) * 16);
    const uint32_t boff = (uint32_t)((lane & 7) * 80 + ((lane >> 3) & 1) * 16);

    const int nt = K >> 5;
    for (int kt = 0; kt < nt; kt++) {
        cpwait<0>();
        __syncthreads();
        if (kt + 1 < nt) load_stage((kt + 1) & 1, kt + 1);

        const uint32_t base = smb + (kt & 1) * 4 * BG_HB;
        const uint32_t aHi = base + 0 * BG_HB + (uint32_t)(wm * 64 * 80) + aoff;
        const uint32_t aLo = base + 1 * BG_HB + (uint32_t)(wm * 64 * 80) + aoff;
        const uint32_t bHi = base + 2 * BG_HB + (uint32_t)(wn * 32 * 80) + boff;
        const uint32_t bLo = base + 3 * BG_HB + (uint32_t)(wn * 32 * 80) + boff;
#pragma unroll
        for (int ks = 0; ks < 2; ks++) {
            const uint32_t ko = ks * 32;
            uint32_t ah[4][4], bh[4][2];
#pragma unroll
            for (int mt = 0; mt < 4; mt++)
                ldsm4(ah[mt], aHi + mt * (16 * 80) + ko);
#pragma unroll
            for (int ntt = 0; ntt < 4; ntt++)
                ldsm2(bh[ntt], bHi + ntt * (8 * 80) + ko);
#pragma unroll
            for (int mt = 0; mt < 4; mt++)
#pragma unroll
                for (int ntt = 0; ntt < 4; ntt++)
                    mma16bf(acc[mt][ntt][0], acc[mt][ntt][1], acc[mt][ntt][2], acc[mt][ntt][3],
                            ah[mt][0], ah[mt][1], ah[mt][2], ah[mt][3],
                            bh[ntt][0], bh[ntt][1]);

            uint32_t al[4][4];
#pragma unroll
            for (int mt = 0; mt < 4; mt++)
                ldsm4(al[mt], aLo + mt * (16 * 80) + ko);
#pragma unroll
            for (int mt = 0; mt < 4; mt++)
#pragma unroll
                for (int ntt = 0; ntt < 4; ntt++)
                    mma16bf(acc[mt][ntt][0], acc[mt][ntt][1], acc[mt][ntt][2], acc[mt][ntt][3],
                            al[mt][0], al[mt][1], al[mt][2], al[mt][3],
                            bh[ntt][0], bh[ntt][1]);

#pragma unroll
            for (int ntt = 0; ntt < 4; ntt++)
                ldsm2(bh[ntt], bLo + ntt * (8 * 80) + ko);
#pragma unroll
            for (int mt = 0; mt < 4; mt++)
#pragma unroll
                for (int ntt = 0; ntt < 4; ntt++)
                    mma16bf(acc[mt][ntt][0], acc[mt][ntt][1], acc[mt][ntt][2], acc[mt][ntt][3],
                            ah[mt][0], ah[mt][1], ah[mt][2], ah[mt][3],
                            bh[ntt][0], bh[ntt][1]);
        }
        __syncthreads();
    }

    // Epilogue: += into C (fp32)
#pragma unroll
    for (int mt = 0; mt < 4; mt++) {
        const int r0 = bm + wm * 64 + mt * 16 + l4;
#pragma unroll
        for (int ntt = 0; ntt < 4; ntt++) {
            const int c0 = bn + wn * 32 + ntt * 8 + lr * 2;
            float* p0 = C + (size_t)r0 * N + c0;
            float* p1 = p0 + (size_t)8 * N;
            const float2 o0 = *(const float2*)p0;
            const float2 o1 = *(const float2*)p1;
            *(float2*)p0 = make_float2(acc[mt][ntt][0] + o0.x, acc[mt][ntt][1] + o0.y);
            *(float2*)p1 = make_float2(acc[mt][ntt][2] + o1.x, acc[mt][ntt][3] + o1.y);
        }
    }
}

// ---------------------------------------------------------------------------
// xred32: reduce split-K partials for B/C columns (64..95) only.
// ---------------------------------------------------------------------------
__global__ void xred32_kernel()
{
    const int i = blockIdx.x * 256 + threadIdx.x;   // Tt*32
    const int row = i >> 5;
    const int c   = 64 + (i & 31);
    float s = 0.f;
#pragma unroll
    for (int z = 0; z < XSK; z++) s += g_xpart[(size_t)z * Tt * 96 + row * 96 + c];
    g_xdbl[row * 96 + c] = s;
}

// ---------------------------------------------------------------------------
// LayerNorm (output rounded to tf32 — feeds GEMMs only)
// ---------------------------------------------------------------------------
__global__ void ln_kernel(const float* __restrict__ x, const float* __restrict__ w,
                          const float* __restrict__ b, float* __restrict__ o)
{
    __shared__ float s1[8], s2[8];
    const int row = blockIdx.x;
    const int tid = threadIdx.x;
    const float4 v = ((const float4*)(x + (size_t)row * DM))[tid];
    float s  = v.x + v.y + v.z + v.w;
    float ss = v.x * v.x + v.y * v.y + v.z * v.z + v.w * v.w;
#pragma unroll
    for (int off = 16; off; off >>= 1) {
        s  += __shfl_xor_sync(0xffffffffu, s,  off);
        ss += __shfl_xor_sync(0xffffffffu, ss, off);
    }
    if ((tid & 31) == 0) { s1[tid >> 5] = s; s2[tid >> 5] = ss; }
    __syncthreads();
    float ts = 0.f, tss = 0.f;
#pragma unroll
    for (int i = 0; i < 8; i++) { ts += s1[i]; tss += s2[i]; }
    const float mean = ts * (1.f / DM);
    const float var  = tss * (1.f / DM) - mean * mean;
    const float rstd = rsqrtf(var + 1e-5f);
    const float4 wv = ((const float4*)w)[tid];
    const float4 bv = ((const float4*)b)[tid];
    float4 r;
    r.x = rtf((v.x - mean) * rstd * wv.x + bv.x);
    r.y = rtf((v.y - mean) * rstd * wv.y + bv.y);
    r.z = rtf((v.z - mean) * rstd * wv.z + bv.z);
    r.w = rtf((v.w - mean) * rstd * wv.w + bv.w);
    ((float4*)(o + (size_t)row * DM))[tid] = r;
}

// ---------------------------------------------------------------------------
// Depthwise causal conv (K=4) + SiLU (output rounded to tf32)
// ---------------------------------------------------------------------------
__global__ void conv_kernel(const float* __restrict__ cw, const float* __restrict__ cb)
{
    const int idx = blockIdx.x * 256 + threadIdx.x;
    const int e  = idx & (EE - 1);
    const int bt = idx >> 11;
    const int t  = bt & (Ll - 1);
    float acc = cb[e];
    const float* base = g_xz + (size_t)bt * (2 * EE) + e;
#pragma unroll
    for (int k = 0; k < 4; k++) {
        const int tt = t - 3 + k;
        if (tt >= 0) acc += cw[e * 4 + k] * base[(size_t)(k - 3) * (2 * EE)];
    }
    g_xm[idx] = rtf(acc / (1.f + __expf(-acc)));
}

// ---------------------------------------------------------------------------
// dtproj GEMM + softplus (fp32), fused split-K reduction of x_dbl cols 0..63.
// ---------------------------------------------------------------------------
__global__ __launch_bounds__(256)
void dt_kernel(const float* __restrict__ W, const float* __restrict__ db)
{
    __shared__ float Xs[16][64];
    __shared__ float Wt[64][132];
    const int tid = threadIdx.x;
    const int bm = blockIdx.y * 16;
    const int bn = blockIdx.x * 128;
    {
        const int m  = tid >> 4;
        const int k4 = (tid & 15) << 2;
        const size_t off = (size_t)(bm + m) * 96 + k4;
        float4 a = make_float4(0.f, 0.f, 0.f, 0.f);
#pragma unroll
        for (int z = 0; z < XSK; z++) {
            const float4 v = *(const float4*)(g_xpart + (size_t)z * Tt * 96 + off);
            a.x += v.x; a.y += v.y; a.z += v.z; a.w += v.w;
        }
        *(float4*)&Xs[m][k4] = a;
    }
#pragma unroll
    for (int r = 0; r < 8; r++) {
        const int idx = tid + 256 * r;
        const int n  = idx >> 4;
        const int k4 = (idx & 15) << 2;
        float4 v = *(const float4*)(W + (size_t)(bn + n) * 64 + k4);
        Wt[k4 + 0][n] = v.x; Wt[k4 + 1][n] = v.y;
        Wt[k4 + 2][n] = v.z; Wt[k4 + 3][n] = v.w;
    }
    __syncthreads();

    const int nb = (tid & 31) << 2;
    const int m0 = tid >> 5;
    float acc[2][4];
#pragma unroll
    for (int i = 0; i < 2; i++)
#pragma unroll
        for (int j = 0; j < 4; j++) acc[i][j] = 0.f;
#pragma unroll
    for (int k = 0; k < 64; k++) {
        const float4 w = *(const float4*)&Wt[k][nb];
        const float x0 = Xs[m0][k];
        const float x1 = Xs[m0 + 8][k];
        acc[0][0] = fmaf(x0, w.x, acc[0][0]); acc[0][1] = fmaf(x0, w.y, acc[0][1]);
        acc[0][2] = fmaf(x0, w.z, acc[0][2]); acc[0][3] = fmaf(x0, w.w, acc[0][3]);
        acc[1][0] = fmaf(x1, w.x, acc[1][0]); acc[1][1] = fmaf(x1, w.y, acc[1][1]);
        acc[1][2] = fmaf(x1, w.z, acc[1][2]); acc[1][3] = fmaf(x1, w.w, acc[1][3]);
    }
#pragma unroll
    for (int i = 0; i < 2; i++) {
        const int row = bm + m0 + 8 * i;
#pragma unroll
        for (int j = 0; j < 4; j++) {
            float v = acc[i][j] + db[bn + nb + j];
            v = (v > 20.f) ? v : log1pf(expf(v));
            g_dt[(size_t)row * EE + bn + nb + j] = v;
        }
    }
}

// ---------------------------------------------------------------------------
// Selective scan: chunked smem staging + x4-unrolled shfl reductions.
// y emitted as bf16 hi/lo pair (feeds split-bf16 outproj).
// ---------------------------------------------------------------------------
#define CH 64
__global__ __launch_bounds__(128)
void scan_kernel(int layer, const float* __restrict__ Dl)
{
    __shared__ float s_dt[2][CH][8];
    __shared__ float s_u [2][CH][8];
    __shared__ float s_zg[2][CH][8];
    __shared__ float s_B [2][CH][16];
    __shared__ float s_C [2][CH][16];
    __shared__ float s_y [CH][8];

    const int b   = blockIdx.y;
    const int e0  = blockIdx.x * 8;
    const int tid = threadIdx.x;
    const int eg  = tid >> 4;
    const int n   = tid & 15;

    const float Av = g_A[(size_t)layer * EE * NN + (e0 + eg) * NN + n];
    const float Dv = Dl[e0 + eg];

    auto load_chunk = [&](int buf, int t0) {
        const size_t bt0 = (size_t)(b * Ll + t0);
#pragma unroll
        for (int it = 0; it < 4; it++) {
            const int idx = tid + it * 128;
            const int t = idx >> 3, e = idx & 7;
            cp4(&s_dt[buf][t][e], &g_dt[(bt0 + t) * EE + e0 + e]);
            cp4(&s_u [buf][t][e], &g_xm[(bt0 + t) * EE + e0 + e]);
            cp4(&s_zg[buf][t][e], &g_xz[(bt0 + t) * (2 * EE) + EE + e0 + e]);
        }
#pragma unroll
        for (int it = 0; it < 8; it++) {
            const int idx = tid + it * 128;
            const int t = idx >> 4, nn = idx & 15;
            cp4(&s_B[buf][t][nn], &g_xdbl[(bt0 + t) * 96 + 64 + nn]);
            cp4(&s_C[buf][t][nn], &g_xdbl[(bt0 + t) * 96 + 80 + nn]);
        }
        cpcommit();
    };

    load_chunk(0, 0);

    float h = 0.f;
    const int NC = Ll / CH;
    for (int c = 0; c < NC; c++) {
        const int buf = c & 1;
        if (c + 1 < NC) { load_chunk(buf ^ 1, (c + 1) * CH); cpwait<1>(); }
        else            { cpwait<0>(); }
        __syncthreads();

#pragma unroll 4
        for (int tb = 0; tb < CH; tb += 4) {
            float p[4];
#pragma unroll
            for (int j = 0; j < 4; j++) {
                const float dt = s_dt[buf][tb + j][eg];
                const float uu = s_u [buf][tb + j][eg];
                const float Bv = s_B [buf][tb + j][n];
                const float Cv = s_C [buf][tb + j][n];
                const float dA = __expf(dt * Av);
                h = fmaf(dA, h, dt * uu * Bv);
                p[j] = h * Cv;
            }
#pragma unroll
            for (int off = 8; off; off >>= 1)
#pragma unroll
                for (int j = 0; j < 4; j++)
                    p[j] += __shfl_xor_sync(0xffffffffu, p[j], off);
            if (n == 0) {
#pragma unroll
                for (int j = 0; j < 4; j++) {
                    const float uu = s_u [buf][tb + j][eg];
                    const float zg = s_zg[buf][tb + j][eg];
                    const float sil = zg / (1.f + __expf(-zg));
                    s_y[tb + j][eg] = (p[j] + uu * Dv) * sil;
                }
            }
        }
        __syncthreads();

        const size_t bt0 = (size_t)(b * Ll + c * CH);
#pragma unroll
        for (int it = 0; it < 4; it++) {
            const int idx = tid + it * 128;
            const int t = idx >> 3, e = idx & 7;
            const float yv = s_y[t][e];
            const __nv_bfloat16 hi = __float2bfloat16(yv);
            const __nv_bfloat16 lo = __float2bfloat16(yv - __bfloat162float(hi));
            g_y_hi[(bt0 + t) * EE + e0 + e] = hi;
            g_y_lo[(bt0 + t) * EE + e0 + e] = lo;
        }
    }
}

// ---------------------------------------------------------------------------
extern "C" void kernel_launch(void* const* d_in, const int* in_sizes, int n_in,
                              void* d_out, int out_size)
{
    const float* x         = (const float*)d_in[0];
    const float* ip_w      = (const float*)d_in[2];
    const float* ip_b      = (const float*)d_in[3];
    const float* ln_w      = (const float*)d_in[4];
    const float* ln_b      = (const float*)d_in[5];
    const float* inproj_w  = (const float*)d_in[6];
    const float* conv_w    = (const float*)d_in[7];
    const float* conv_b    = (const float*)d_in[8];
    const float* xproj_w   = (const float*)d_in[9];
    const float* dtproj_w  = (const float*)d_in[10];
    const float* dtproj_b  = (const float*)d_in[11];
    const float* A_log     = (const float*)d_in[12];
    const float* Dp        = (const float*)d_in[13];
    const float* outproj_w = (const float*)d_in[14];
    const float* fnorm_w   = (const float*)d_in[15];
    const float* fnorm_b   = (const float*)d_in[16];
    const float* op_w      = (const float*)d_in[17];
    const float* op_b      = (const float*)d_in[18];
    float* out = (float*)d_out;

    float *p_h, *p_hn, *p_xz, *p_xm, *p_xr, *p_xpart;
    float *p_wip, *p_winproj, *p_wxproj, *p_wop;
    __nv_bfloat16 *p_wouthi, *p_woutlo, *p_yhi, *p_ylo;
    cudaGetSymbolAddress((void**)&p_h,       g_h);
    cudaGetSymbolAddress((void**)&p_hn,      g_hn);
    cudaGetSymbolAddress((void**)&p_xz,      g_xz);
    cudaGetSymbolAddress((void**)&p_xm,      g_xm);
    cudaGetSymbolAddress((void**)&p_xr,      g_xr);
    cudaGetSymbolAddress((void**)&p_xpart,   g_xpart);
    cudaGetSymbolAddress((void**)&p_wip,     g_wip);
    cudaGetSymbolAddress((void**)&p_winproj, g_winproj);
    cudaGetSymbolAddress((void**)&p_wxproj,  g_wxproj);
    cudaGetSymbolAddress((void**)&p_wop,     g_wop);
    cudaGetSymbolAddress((void**)&p_wouthi,  g_wout_hi);
    cudaGetSymbolAddress((void**)&p_woutlo,  g_wout_lo);
    cudaGetSymbolAddress((void**)&p_yhi,     g_y_hi);
    cudaGetSymbolAddress((void**)&p_ylo,     g_y_lo);

    const int SM4 = 3 * (128 * 20 + 128 * 20) * 4;
    const int SM3 = 3 * (128 * 20 +  96 * 20) * 4;
    cudaFuncSetAttribute(tgemm<2,4,0,0,0>, cudaFuncAttributeMaxDynamicSharedMemorySize, SM4);
    cudaFuncSetAttribute(tgemm<2,4,0,1,0>, cudaFuncAttributeMaxDynamicSharedMemorySize, SM4);
    cudaFuncSetAttribute(tgemm<2,3,0,0,1>, cudaFuncAttributeMaxDynamicSharedMemorySize, SM3);
    cudaFuncSetAttribute(bgemm, cudaFuncAttributeMaxDynamicSharedMemorySize, BG_SMEM);

    // (1) fused prep
    {
        const int nblk = (int)((P_TOT + 255) / 256);
        prep_all<<<nblk, 256>>>((const float4*)x, (const float4*)ip_w,
                                (const float4*)inproj_w, (const float4*)xproj_w,
                                (const float4*)outproj_w, (const float4*)op_w, A_log);
    }

    // (2) h = x @ ip_w^T + ip_b
    tgemm<2,4,0,1,0><<<dim3(DM / 128, Tt / 128), 256, SM4>>>(
        p_xr, p_wip, ip_b, p_h, Tt, DM, DIN, DIN);

    for (int l = 0; l < NLr; l++) {
        // (3) layernorm
        ln_kernel<<<Tt, 256>>>(p_h, ln_w + (size_t)l * DM, ln_b + (size_t)l * DM, p_hn);

        // (4) xz = hn @ inproj_w^T   [T, 4096]   <- profiled slot on l=0
        tgemm<2,4,0,0,0><<<dim3((2 * EE) / 128, Tt / 128), 256, SM4>>>(
            p_hn, p_winproj + (size_t)l * 2 * EE * DM, nullptr, p_xz, Tt, 2 * EE, DM, DM);

        conv_kernel<<<(Tt * EE) / 256, 256>>>(conv_w + (size_t)l * EE * 4,
                                              conv_b + (size_t)l * EE);

        // x_dbl partials = xm @ xproj_w^T  (split-K)
        tgemm<2,3,0,0,1><<<dim3(1, Tt / 128, XSK), 192, SM3>>>(
            p_xm, p_wxproj + (size_t)l * 96 * EE, nullptr, p_xpart,
            Tt, 96, EE / XSK, EE);

        xred32_kernel<<<(Tt * 32) / 256, 256>>>();

        dt_kernel<<<dim3(EE / 128, Tt / 16), 256>>>(dtproj_w + (size_t)l * EE * RR,
                                                    dtproj_b + (size_t)l * EE);

        scan_kernel<<<dim3(EE / 8, Bb), 128>>>(l, Dp + (size_t)l * EE);

        // h += y @ outproj_w^T   (split-bf16 probe)
        bgemm<<<dim3(DM / 128, Tt / 128), 256, BG_SMEM>>>(
            p_yhi, p_ylo,
            p_wouthi + (size_t)l * DM * EE, p_woutlo + (size_t)l * DM * EE,
            p_h, Tt, DM, EE);
    }

    ln_kernel<<<Tt, 256>>>(p_h, fnorm_w, fnorm_b, p_hn);

    // out = hn @ op_w^T + op_b   [T, 512]
    tgemm<2,4,0,1,0><<<dim3(DIN / 128, Tt / 128), 256, SM4>>>(
        p_hn, p_wop, op_b, out, Tt, DIN, DM, DM);
}

// round 12
// speedup vs baseline: 1.6469x; 1.6469x over previous
#include <cuda_runtime.h>
#include <math.h>
#include <stdint.h>

// Problem constants
#define Bb   2
#define Ll   1024
#define Tt   2048        // Bb*Ll tokens
#define DIN  512
#define DM   1024
#define NLr  4
#define EE   2048
#define NN   16
#define RR   64
#define XSK  16          // split-K factor for xproj

// ---------------- scratch (device globals; no runtime allocation) ----------
__device__ float g_h   [Tt * DM];
__device__ float g_hn  [Tt * DM];
__device__ float g_xz  [Tt * 2 * EE];
__device__ float g_xm  [Tt * EE];
__device__ float g_xdbl[Tt * 96];
__device__ float g_dt  [Tt * EE];
__device__ float g_y   [Tt * EE];
__device__ float g_A   [NLr * EE * NN];
__device__ float g_xr  [Tt * DIN];                 // tf32-rounded x
__device__ float g_xpart[XSK * Tt * 96];           // xproj split-K partials
__device__ float g_gp  [4 * Tt * DIN];             // generic split-K partials
                                                   // (= 2*Tt*DM = 4*Tt*DIN floats)
// tf32-rounded weights
__device__ float g_wip     [DM * DIN];
__device__ float g_winproj [NLr * 2 * EE * DM];
__device__ float g_wxproj  [NLr * 96 * EE];
__device__ float g_woutproj[NLr * DM * EE];
__device__ float g_wop     [DIN * DM];

// ---------------------------------------------------------------------------
// helpers
// ---------------------------------------------------------------------------
__device__ __forceinline__ uint32_t f2tf(float x) {
    uint32_t r;
    asm("cvt.rna.tf32.f32 %0, %1;" : "=r"(r) : "f"(x));
    return r;
}
__device__ __forceinline__ float rtf(float x) { return __uint_as_float(f2tf(x)); }

__device__ __forceinline__ void mma8(float& d0, float& d1, float& d2, float& d3,
                                     uint32_t a0, uint32_t a1, uint32_t a2, uint32_t a3,
                                     uint32_t b0, uint32_t b1) {
    asm volatile(
        "mma.sync.aligned.m16n8k8.row.col.f32.tf32.tf32.f32 "
        "{%0,%1,%2,%3}, {%4,%5,%6,%7}, {%8,%9}, {%0,%1,%2,%3};"
        : "+f"(d0), "+f"(d1), "+f"(d2), "+f"(d3)
        : "r"(a0), "r"(a1), "r"(a2), "r"(a3), "r"(b0), "r"(b1));
}
__device__ __forceinline__ void ldsm4(uint32_t* r, uint32_t a) {
    asm volatile("ldmatrix.sync.aligned.m8n8.x4.shared.b16 {%0,%1,%2,%3}, [%4];"
                 : "=r"(r[0]), "=r"(r[1]), "=r"(r[2]), "=r"(r[3]) : "r"(a));
}
__device__ __forceinline__ void ldsm2(uint32_t* r, uint32_t a) {
    asm volatile("ldmatrix.sync.aligned.m8n8.x2.shared.b16 {%0,%1}, [%2];"
                 : "=r"(r[0]), "=r"(r[1]) : "r"(a));
}
__device__ __forceinline__ void cp16(void* dst, const void* src) {
    uint32_t d = (uint32_t)__cvta_generic_to_shared(dst);
    asm volatile("cp.async.cg.shared.global [%0], [%1], 16;" :: "r"(d), "l"(src));
}
__device__ __forceinline__ void cp4(void* dst, const void* src) {
    uint32_t d = (uint32_t)__cvta_generic_to_shared(dst);
    asm volatile("cp.async.ca.shared.global [%0], [%1], 4;" :: "r"(d), "l"(src));
}
__device__ __forceinline__ void cpcommit() { asm volatile("cp.async.commit_group;"); }
template<int NG> __device__ __forceinline__ void cpwait() {
    asm volatile("cp.async.wait_group %0;" :: "n"(NG));
}

// ---------------------------------------------------------------------------
// Fused prep: tf32-round all GEMM operands + A transform, one launch.
// ---------------------------------------------------------------------------
#define P_S0 ((size_t)(Tt * DIN / 4))                       // x
#define P_S1 (P_S0 + (size_t)(DM * DIN / 4))                // ip_w
#define P_S2 (P_S1 + (size_t)(NLr * 2 * EE * DM / 4))       // inproj_w
#define P_S3 (P_S2 + (size_t)(NLr * 96 * EE / 4))           // xproj_w
#define P_S4 (P_S3 + (size_t)(NLr * DM * EE / 4))           // outproj_w
#define P_S5 (P_S4 + (size_t)(DIN * DM / 4))                // op_w
#define P_TOT (P_S5 + (size_t)(NLr * EE * NN))              // + A elems

__global__ void prep_all(const float4* __restrict__ x,   const float4* __restrict__ ipw,
                         const float4* __restrict__ inw, const float4* __restrict__ xpw,
                         const float4* __restrict__ otw, const float4* __restrict__ opw,
                         const float* __restrict__ A_log)
{
    const size_t i = (size_t)blockIdx.x * 256 + threadIdx.x;
    if (i < P_S5) {
        const float4* s; float4* d; size_t j;
        if      (i < P_S0) { s = x;   d = (float4*)g_xr;       j = i; }
        else if (i < P_S1) { s = ipw; d = (float4*)g_wip;      j = i - P_S0; }
        else if (i < P_S2) { s = inw; d = (float4*)g_winproj;  j = i - P_S1; }
        else if (i < P_S3) { s = xpw; d = (float4*)g_wxproj;   j = i - P_S2; }
        else if (i < P_S4) { s = otw; d = (float4*)g_woutproj; j = i - P_S3; }
        else               { s = opw; d = (float4*)g_wop;      j = i - P_S4; }
        float4 v = s[j];
        v.x = rtf(v.x); v.y = rtf(v.y); v.z = rtf(v.z); v.w = rtf(v.w);
        d[j] = v;
    } else if (i < P_TOT) {
        const size_t j = i - P_S5;
        g_A[j] = -expf(A_log[j]);
    }
}

// ---------------------------------------------------------------------------
// TF32 HMMA GEMM (proven R5/R10 config): 3-stage cp.async + ldmatrix.
// SK: split-K over blockIdx.z; chunk length = K arg; C -> partials [z][M][N].
// ---------------------------------------------------------------------------
template<int WMW, int WNW, int BETA, int BIAS, int SK>
__global__ __launch_bounds__(WMW * WNW * 32, 2)
void tgemm(const float* __restrict__ A, const float* __restrict__ W,
           const float* __restrict__ bias, float* __restrict__ C,
           int M, int N, int K, int lda)
{
    constexpr int NT  = WMW * WNW * 32;
    constexpr int BM  = WMW * 64;
    constexpr int BN  = WNW * 32;
    constexpr int ST  = 3;
    constexpr int AW  = BM * 20;
    constexpr int BW  = BN * 20;
    constexpr int AIT = (BM * 4 + NT - 1) / NT;
    constexpr int BIT = (BN * 4 + NT - 1) / NT;

    extern __shared__ float dynsm[];

    if (SK) {
        A += (size_t)blockIdx.z * K;
        W += (size_t)blockIdx.z * K;
        C += (size_t)blockIdx.z * M * N;
    }

    const int tid  = threadIdx.x;
    const int bm   = blockIdx.y * BM;
    const int bn   = blockIdx.x * BN;
    const int wid  = tid >> 5;
    const int lane = tid & 31;
    const int wm   = wid % WMW;
    const int wn   = wid / WMW;
    const int l4   = lane >> 2;
    const int lr   = lane & 3;

    const float* Ag = A + (size_t)bm * lda;
    const float* Wg = W + (size_t)bn * lda;

    float acc[4][4][4];
#pragma unroll
    for (int i = 0; i < 4; i++)
#pragma unroll
        for (int j = 0; j < 4; j++)
#pragma unroll
            for (int k = 0; k < 4; k++) acc[i][j][k] = 0.f;

    auto load_stage = [&](int st, int kt) {
        float* As = dynsm + st * AW;
        float* Bs = dynsm + ST * AW + st * BW;
#pragma unroll
        for (int i = 0; i < AIT; i++) {
            const int f = tid + i * NT;
            if (f < BM * 4) {
                const int row = f >> 2, c = (f & 3) << 2;
                cp16(As + row * 20 + c, Ag + (size_t)row * lda + kt * 16 + c);
            }
        }
#pragma unroll
        for (int i = 0; i < BIT; i++) {
            const int f = tid + i * NT;
            if (f < BN * 4) {
                const int row = f >> 2, c = (f & 3) << 2;
                cp16(Bs + row * 20 + c, Wg + (size_t)row * lda + kt * 16 + c);
            }
        }
        cpcommit();
    };

    load_stage(0, 0);
    load_stage(1, 1);

    const int sub  = lane >> 3, tr = lane & 7;
    const int aoff = ((sub & 1) * 8 + tr) * 20 + (sub >> 1) * 4;
    const int l15  = lane & 15;
    const int boff = (l15 & 7) * 20 + (l15 >> 3) * 4;
    const uint32_t Au = (uint32_t)__cvta_generic_to_shared(dynsm);
    const uint32_t Bu = (uint32_t)__cvta_generic_to_shared(dynsm + ST * AW);

    const int nt = K >> 4;
    for (int kt = 0; kt < nt; kt++) {
        cpwait<1>();
        __syncthreads();
        if (kt + 2 < nt) load_stage((kt + 2) % ST, kt + 2);

        const int st = kt % ST;
        const uint32_t aB = Au + (uint32_t)(st * AW + wm * 64 * 20 + aoff) * 4;
        const uint32_t bB = Bu + (uint32_t)(st * BW + wn * 32 * 20 + boff) * 4;
#pragma unroll
        for (int ks = 0; ks < 2; ks++) {
            uint32_t af[4][4], bf[4][2];
#pragma unroll
            for (int mt = 0; mt < 4; mt++)
                ldsm4(af[mt], aB + (uint32_t)(mt * 16 * 20 + ks * 8) * 4);
#pragma unroll
            for (int ntt = 0; ntt < 4; ntt++)
                ldsm2(bf[ntt], bB + (uint32_t)(ntt * 8 * 20 + ks * 8) * 4);
#pragma unroll
            for (int mt = 0; mt < 4; mt++)
#pragma unroll
                for (int ntt = 0; ntt < 4; ntt++)
                    mma8(acc[mt][ntt][0], acc[mt][ntt][1], acc[mt][ntt][2], acc[mt][ntt][3],
                         af[mt][0], af[mt][1], af[mt][2], af[mt][3],
                         bf[ntt][0], bf[ntt][1]);
        }
    }

#pragma unroll
    for (int mt = 0; mt < 4; mt++) {
        const int r0 = bm + wm * 64 + mt * 16 + l4;
#pragma unroll
        for (int ntt = 0; ntt < 4; ntt++) {
            const int c0 = bn + wn * 32 + ntt * 8 + lr * 2;
            float* p0 = C + (size_t)r0 * N + c0;
            float* p1 = p0 + (size_t)8 * N;
            float v0 = acc[mt][ntt][0], v1 = acc[mt][ntt][1];
            float v2 = acc[mt][ntt][2], v3 = acc[mt][ntt][3];
            if (BIAS) {
                const float b0 = bias[c0], b1 = bias[c0 + 1];
                v0 += b0; v1 += b1; v2 += b0; v3 += b1;
            }
            if (BETA) {
                const float2 o0 = *(const float2*)p0;
                const float2 o1 = *(const float2*)p1;
                v0 += o0.x; v1 += o0.y; v2 += o1.x; v3 += o1.y;
            }
            *(float2*)p0 = make_float2(v0, v1);
            *(float2*)p1 = make_float2(v2, v3);
        }
    }
}

// ---------------------------------------------------------------------------
// xred32: reduce xproj split-K partials for B/C columns (64..95) only.
// ---------------------------------------------------------------------------
__global__ void xred32_kernel()
{
    const int i = blockIdx.x * 256 + threadIdx.x;   // Tt*32
    const int row = i >> 5;
    const int c   = 64 + (i & 31);
    float s = 0.f;
#pragma unroll
    for (int z = 0; z < XSK; z++) s += g_xpart[(size_t)z * Tt * 96 + row * 96 + c];
    g_xdbl[row * 96 + c] = s;
}

// ---------------------------------------------------------------------------
// LayerNorm variants with fused split-K reduction of the residual stream.
// ln0: h = gp0 + gp1 + bias;  hn = LN(h)    (first layer, after ip GEMM)
// lnr: h = h + gp0 + gp1;     hn = LN(h)    (after each outproj; also final)
// LN output rounded to tf32 (feeds GEMMs only).
// ---------------------------------------------------------------------------
__device__ __forceinline__ void ln_core(float4 v, const float* w, const float* b,
                                        float* o, int row, int tid,
                                        float* s1, float* s2)
{
    float s  = v.x + v.y + v.z + v.w;
    float ss = v.x * v.x + v.y * v.y + v.z * v.z + v.w * v.w;
#pragma unroll
    for (int off = 16; off; off >>= 1) {
        s  += __shfl_xor_sync(0xffffffffu, s,  off);
        ss += __shfl_xor_sync(0xffffffffu, ss, off);
    }
    if ((tid & 31) == 0) { s1[tid >> 5] = s; s2[tid >> 5] = ss; }
    __syncthreads();
    float ts = 0.f, tss = 0.f;
#pragma unroll
    for (int i = 0; i < 8; i++) { ts += s1[i]; tss += s2[i]; }
    const float mean = ts * (1.f / DM);
    const float var  = tss * (1.f / DM) - mean * mean;
    const float rstd = rsqrtf(var + 1e-5f);
    const float4 wv = ((const float4*)w)[tid];
    const float4 bv = ((const float4*)b)[tid];
    float4 r;
    r.x = rtf((v.x - mean) * rstd * wv.x + bv.x);
    r.y = rtf((v.y - mean) * rstd * wv.y + bv.y);
    r.z = rtf((v.z - mean) * rstd * wv.z + bv.z);
    r.w = rtf((v.w - mean) * rstd * wv.w + bv.w);
    ((float4*)(o + (size_t)row * DM))[tid] = r;
}

__global__ void ln0_kernel(const float* __restrict__ bias,
                           const float* __restrict__ w, const float* __restrict__ b)
{
    __shared__ float s1[8], s2[8];
    const int row = blockIdx.x;
    const int tid = threadIdx.x;
    const float4 p0 = ((const float4*)(g_gp + (size_t)row * DM))[tid];
    const float4 p1 = ((const float4*)(g_gp + (size_t)Tt * DM + (size_t)row * DM))[tid];
    const float4 bb = ((const float4*)bias)[tid];
    float4 v;
    v.x = p0.x + p1.x + bb.x; v.y = p0.y + p1.y + bb.y;
    v.z = p0.z + p1.z + bb.z; v.w = p0.w + p1.w + bb.w;
    ((float4*)(g_h + (size_t)row * DM))[tid] = v;
    ln_core(v, w, b, g_hn, row, tid, s1, s2);
}

__global__ void lnr_kernel(const float* __restrict__ w, const float* __restrict__ b)
{
    __shared__ float s1[8], s2[8];
    const int row = blockIdx.x;
    const int tid = threadIdx.x;
    const float4 hv = ((const float4*)(g_h + (size_t)row * DM))[tid];
    const float4 p0 = ((const float4*)(g_gp + (size_t)row * DM))[tid];
    const float4 p1 = ((const float4*)(g_gp + (size_t)Tt * DM + (size_t)row * DM))[tid];
    float4 v;
    v.x = hv.x + p0.x + p1.x; v.y = hv.y + p0.y + p1.y;
    v.z = hv.z + p0.z + p1.z; v.w = hv.w + p0.w + p1.w;
    ((float4*)(g_h + (size_t)row * DM))[tid] = v;
    ln_core(v, w, b, g_hn, row, tid, s1, s2);
}

// ---------------------------------------------------------------------------
// opred: out = sum_{z<4} gp[z] + op_b   (final projection split-K reduce)
// ---------------------------------------------------------------------------
__global__ void opred_kernel(const float4* __restrict__ opb, float4* __restrict__ out)
{
    const int i = blockIdx.x * 256 + threadIdx.x;   // Tt*DIN/4
    const float4* g = (const float4*)g_gp;
    const int P = Tt * DIN / 4;
    const float4 a = g[i], b4 = g[P + i], c = g[2 * P + i], d = g[3 * P + i];
    const float4 bb = opb[i & (DIN / 4 - 1)];
    float4 r;
    r.x = a.x + b4.x + c.x + d.x + bb.x;
    r.y = a.y + b4.y + c.y + d.y + bb.y;
    r.z = a.z + b4.z + c.z + d.z + bb.z;
    r.w = a.w + b4.w + c.w + d.w + bb.w;
    out[i] = r;
}

// ---------------------------------------------------------------------------
// Depthwise causal conv (K=4) + SiLU (output rounded to tf32)
// ---------------------------------------------------------------------------
__global__ void conv_kernel(const float* __restrict__ cw, const float* __restrict__ cb)
{
    const int idx = blockIdx.x * 256 + threadIdx.x;
    const int e  = idx & (EE - 1);
    const int bt = idx >> 11;
    const int t  = bt & (Ll - 1);
    float acc = cb[e];
    const float* base = g_xz + (size_t)bt * (2 * EE) + e;
#pragma unroll
    for (int k = 0; k < 4; k++) {
        const int tt = t - 3 + k;
        if (tt >= 0) acc += cw[e * 4 + k] * base[(size_t)(k - 3) * (2 * EE)];
    }
    g_xm[idx] = rtf(acc / (1.f + __expf(-acc)));
}

// ---------------------------------------------------------------------------
// dtproj GEMM + softplus (fp32), fused split-K reduction of x_dbl cols 0..63.
// ---------------------------------------------------------------------------
__global__ __launch_bounds__(256)
void dt_kernel(const float* __restrict__ W, const float* __restrict__ db)
{
    __shared__ float Xs[16][64];
    __shared__ float Wt[64][132];
    const int tid = threadIdx.x;
    const int bm = blockIdx.y * 16;
    const int bn = blockIdx.x * 128;
    {
        const int m  = tid >> 4;
        const int k4 = (tid & 15) << 2;
        const size_t off = (size_t)(bm + m) * 96 + k4;
        float4 a = make_float4(0.f, 0.f, 0.f, 0.f);
#pragma unroll
        for (int z = 0; z < XSK; z++) {
            const float4 v = *(const float4*)(g_xpart + (size_t)z * Tt * 96 + off);
            a.x += v.x; a.y += v.y; a.z += v.z; a.w += v.w;
        }
        *(float4*)&Xs[m][k4] = a;
    }
#pragma unroll
    for (int r = 0; r < 8; r++) {
        const int idx = tid + 256 * r;
        const int n  = idx >> 4;
        const int k4 = (idx & 15) << 2;
        float4 v = *(const float4*)(W + (size_t)(bn + n) * 64 + k4);
        Wt[k4 + 0][n] = v.x; Wt[k4 + 1][n] = v.y;
        Wt[k4 + 2][n] = v.z; Wt[k4 + 3][n] = v.w;
    }
    __syncthreads();

    const int nb = (tid & 31) << 2;
    const int m0 = tid >> 5;
    float acc[2][4];
#pragma unroll
    for (int i = 0; i < 2; i++)
#pragma unroll
        for (int j = 0; j < 4; j++) acc[i][j] = 0.f;
#pragma unroll
    for (int k = 0; k < 64; k++) {
        const float4 w = *(const float4*)&Wt[k][nb];
        const float x0 = Xs[m0][k];
        const float x1 = Xs[m0 + 8][k];
        acc[0][0] = fmaf(x0, w.x, acc[0][0]); acc[0][1] = fmaf(x0, w.y, acc[0][1]);
        acc[0][2] = fmaf(x0, w.z, acc[0][2]); acc[0][3] = fmaf(x0, w.w, acc[0][3]);
        acc[1][0] = fmaf(x1, w.x, acc[1][0]); acc[1][1] = fmaf(x1, w.y, acc[1][1]);
        acc[1][2] = fmaf(x1, w.z, acc[1][2]); acc[1][3] = fmaf(x1, w.w, acc[1][3]);
    }
#pragma unroll
    for (int i = 0; i < 2; i++) {
        const int row = bm + m0 + 8 * i;
#pragma unroll
        for (int j = 0; j < 4; j++) {
            float v = acc[i][j] + db[bn + nb + j];
            v = (v > 20.f) ? v : log1pf(expf(v));
            g_dt[(size_t)row * EE + bn + nb + j] = v;
        }
    }
}

// ---------------------------------------------------------------------------
// Selective scan: chunked smem staging + x4-unrolled shfl reductions.
// y rounded to tf32 (feeds outproj GEMM only).
// ---------------------------------------------------------------------------
#define CH 64
__global__ __launch_bounds__(128)
void scan_kernel(int layer, const float* __restrict__ Dl)
{
    __shared__ float s_dt[2][CH][8];
    __shared__ float s_u [2][CH][8];
    __shared__ float s_zg[2][CH][8];
    __shared__ float s_B [2][CH][16];
    __shared__ float s_C [2][CH][16];
    __shared__ float s_y [CH][8];

    const int b   = blockIdx.y;
    const int e0  = blockIdx.x * 8;
    const int tid = threadIdx.x;
    const int eg  = tid >> 4;
    const int n   = tid & 15;

    const float Av = g_A[(size_t)layer * EE * NN + (e0 + eg) * NN + n];
    const float Dv = Dl[e0 + eg];

    auto load_chunk = [&](int buf, int t0) {
        const size_t bt0 = (size_t)(b * Ll + t0);
#pragma unroll
        for (int it = 0; it < 4; it++) {
            const int idx = tid + it * 128;
            const int t = idx >> 3, e = idx & 7;
            cp4(&s_dt[buf][t][e], &g_dt[(bt0 + t) * EE + e0 + e]);
            cp4(&s_u [buf][t][e], &g_xm[(bt0 + t) * EE + e0 + e]);
            cp4(&s_zg[buf][t][e], &g_xz[(bt0 + t) * (2 * EE) + EE + e0 + e]);
        }
#pragma unroll
        for (int it = 0; it < 8; it++) {
            const int idx = tid + it * 128;
            const int t = idx >> 4, nn = idx & 15;
            cp4(&s_B[buf][t][nn], &g_xdbl[(bt0 + t) * 96 + 64 + nn]);
            cp4(&s_C[buf][t][nn], &g_xdbl[(bt0 + t) * 96 + 80 + nn]);
        }
        cpcommit();
    };

    load_chunk(0, 0);

    float h = 0.f;
    const int NC = Ll / CH;
    for (int c = 0; c < NC; c++) {
        const int buf = c & 1;
        if (c + 1 < NC) { load_chunk(buf ^ 1, (c + 1) * CH); cpwait<1>(); }
        else            { cpwait<0>(); }
        __syncthreads();

#pragma unroll 4
        for (int tb = 0; tb < CH; tb += 4) {
            float p[4];
#pragma unroll
            for (int j = 0; j < 4; j++) {
                const float dt = s_dt[buf][tb + j][eg];
                const float uu = s_u [buf][tb + j][eg];
                const float Bv = s_B [buf][tb + j][n];
                const float Cv = s_C [buf][tb + j][n];
                const float dA = __expf(dt * Av);
                h = fmaf(dA, h, dt * uu * Bv);
                p[j] = h * Cv;
            }
#pragma unroll
            for (int off = 8; off; off >>= 1)
#pragma unroll
                for (int j = 0; j < 4; j++)
                    p[j] += __shfl_xor_sync(0xffffffffu, p[j], off);
            if (n == 0) {
#pragma unroll
                for (int j = 0; j < 4; j++) {
                    const float uu = s_u [buf][tb + j][eg];
                    const float zg = s_zg[buf][tb + j][eg];
                    const float sil = zg / (1.f + __expf(-zg));
                    s_y[tb + j][eg] = (p[j] + uu * Dv) * sil;
                }
            }
        }
        __syncthreads();

        const size_t bt0 = (size_t)(b * Ll + c * CH);
#pragma unroll
        for (int it = 0; it < 4; it++) {
            const int idx = tid + it * 128;
            const int t = idx >> 3, e = idx & 7;
            g_y[(bt0 + t) * EE + e0 + e] = rtf(s_y[t][e]);
        }
    }
}

// ---------------------------------------------------------------------------
extern "C" void kernel_launch(void* const* d_in, const int* in_sizes, int n_in,
                              void* d_out, int out_size)
{
    const float* x         = (const float*)d_in[0];
    const float* ip_w      = (const float*)d_in[2];
    const float* ip_b      = (const float*)d_in[3];
    const float* ln_w      = (const float*)d_in[4];
    const float* ln_b      = (const float*)d_in[5];
    const float* inproj_w  = (const float*)d_in[6];
    const float* conv_w    = (const float*)d_in[7];
    const float* conv_b    = (const float*)d_in[8];
    const float* xproj_w   = (const float*)d_in[9];
    const float* dtproj_w  = (const float*)d_in[10];
    const float* dtproj_b  = (const float*)d_in[11];
    const float* A_log     = (const float*)d_in[12];
    const float* Dp        = (const float*)d_in[13];
    const float* outproj_w = (const float*)d_in[14];
    const float* fnorm_w   = (const float*)d_in[15];
    const float* fnorm_b   = (const float*)d_in[16];
    const float* op_w      = (const float*)d_in[17];
    const float* op_b      = (const float*)d_in[18];
    float* out = (float*)d_out;

    float *p_hn, *p_xm, *p_y, *p_xr, *p_xpart, *p_gp;
    float *p_wip, *p_winproj, *p_wxproj, *p_woutproj, *p_wop;
    cudaGetSymbolAddress((void**)&p_hn,       g_hn);
    cudaGetSymbolAddress((void**)&p_xm,       g_xm);
    cudaGetSymbolAddress((void**)&p_y,        g_y);
    cudaGetSymbolAddress((void**)&p_xr,       g_xr);
    cudaGetSymbolAddress((void**)&p_xpart,    g_xpart);
    cudaGetSymbolAddress((void**)&p_gp,       g_gp);
    cudaGetSymbolAddress((void**)&p_wip,      g_wip);
    cudaGetSymbolAddress((void**)&p_winproj,  g_winproj);
    cudaGetSymbolAddress((void**)&p_wxproj,   g_wxproj);
    cudaGetSymbolAddress((void**)&p_woutproj, g_woutproj);
    cudaGetSymbolAddress((void**)&p_wop,      g_wop);
    float* p_xz;
    cudaGetSymbolAddress((void**)&p_xz, g_xz);

    const int SM4 = 3 * (128 * 20 + 128 * 20) * 4;
    const int SM3 = 3 * (128 * 20 +  96 * 20) * 4;
    cudaFuncSetAttribute(tgemm<2,4,0,0,0>, cudaFuncAttributeMaxDynamicSharedMemorySize, SM4);
    cudaFuncSetAttribute(tgemm<2,4,0,0,1>, cudaFuncAttributeMaxDynamicSharedMemorySize, SM4);
    cudaFuncSetAttribute(tgemm<2,3,0,0,1>, cudaFuncAttributeMaxDynamicSharedMemorySize, SM3);

    // (1) fused prep
    {
        const int nblk = (int)((P_TOT + 255) / 256);
        prep_all<<<nblk, 256>>>((const float4*)x, (const float4*)ip_w,
                                (const float4*)inproj_w, (const float4*)xproj_w,
                                (const float4*)outproj_w, (const float4*)op_w, A_log);
    }

    // (2) ip GEMM split-K=2 -> partials (bias added in ln0)
    tgemm<2,4,0,0,1><<<dim3(DM / 128, Tt / 128, 2), 256, SM4>>>(
        p_xr, p_wip, nullptr, p_gp, Tt, DM, DIN / 2, DIN);

    for (int l = 0; l < NLr; l++) {
        // (3) fused residual-reduce + layernorm
        if (l == 0)
            ln0_kernel<<<Tt, 256>>>(ip_b, ln_w, ln_b);
        else
            lnr_kernel<<<Tt, 256>>>(ln_w + (size_t)l * DM, ln_b + (size_t)l * DM);

        // (4) xz = hn @ inproj_w^T   [T, 4096]   <- profiled slot on l=0
        tgemm<2,4,0,0,0><<<dim3((2 * EE) / 128, Tt / 128), 256, SM4>>>(
            p_hn, p_winproj + (size_t)l * 2 * EE * DM, nullptr, p_xz, Tt, 2 * EE, DM, DM);

        conv_kernel<<<(Tt * EE) / 256, 256>>>(conv_w + (size_t)l * EE * 4,
                                              conv_b + (size_t)l * EE);

        // x_dbl partials = xm @ xproj_w^T  (split-K = 16 -> 256 blocks)
        tgemm<2,3,0,0,1><<<dim3(1, Tt / 128, XSK), 192, SM3>>>(
            p_xm, p_wxproj + (size_t)l * 96 * EE, nullptr, p_xpart,
            Tt, 96, EE / XSK, EE);

        xred32_kernel<<<(Tt * 32) / 256, 256>>>();

        dt_kernel<<<dim3(EE / 128, Tt / 16), 256>>>(dtproj_w + (size_t)l * EE * RR,
                                                    dtproj_b + (size_t)l * EE);

        scan_kernel<<<dim3(EE / 8, Bb), 128>>>(l, Dp + (size_t)l * EE);

        // outproj split-K=2 -> partials (residual add fused into next lnr)
        tgemm<2,4,0,0,1><<<dim3(DM / 128, Tt / 128, 2), 256, SM4>>>(
            p_y, p_woutproj + (size_t)l * DM * EE, nullptr, p_gp, Tt, DM, EE / 2, EE);
    }

    // final: h += last outproj partials; hn = LN(h)
    lnr_kernel<<<Tt, 256>>>(fnorm_w, fnorm_b);

    // out = hn @ op_w^T + op_b : split-K=4 -> partials, then reduce+bias
    tgemm<2,4,0,0,1><<<dim3(DIN / 128, Tt / 128, 4), 256, SM4>>>(
        p_hn, p_wop, nullptr, p_gp, Tt, DIN, DM / 4, DM);
    opred_kernel<<<(Tt * DIN / 4) / 256, 256>>>((const float4*)op_b, (float4*)out);
}

// round 14
// speedup vs baseline: 1.6591x; 1.0074x over previous
#include <cuda_runtime.h>
#include <math.h>
#include <stdint.h>

// Problem constants
#define Bb   2
#define Ll   1024
#define Tt   2048        // Bb*Ll tokens
#define DIN  512
#define DM   1024
#define NLr  4
#define EE   2048
#define NN   16
#define RR   64
#define XSK  16          // split-K factor for xproj

// ---------------- scratch (device globals; no runtime allocation) ----------
__device__ float g_h   [Tt * DM];
__device__ float g_hn  [Tt * DM];
__device__ float g_xz  [Tt * 2 * EE];
__device__ float g_xm  [Tt * EE];
__device__ float g_xdbl[Tt * 96];
__device__ float g_dt  [Tt * EE];
__device__ float g_y   [Tt * EE];
__device__ float g_A   [NLr * EE * NN];
__device__ float g_xr  [Tt * DIN];                 // tf32-rounded x
__device__ float g_xpart[XSK * Tt * 96];           // xproj split-K partials
__device__ float g_gp  [4 * Tt * DIN];             // generic split-K partials
// tf32-rounded weights
__device__ float g_wip     [DM * DIN];
__device__ float g_winproj [NLr * 2 * EE * DM];
__device__ float g_wxproj  [NLr * 96 * EE];
__device__ float g_woutproj[NLr * DM * EE];
__device__ float g_wop     [DIN * DM];

// ---------------------------------------------------------------------------
// helpers
// ---------------------------------------------------------------------------
__device__ __forceinline__ uint32_t f2tf(float x) {
    uint32_t r;
    asm("cvt.rna.tf32.f32 %0, %1;" : "=r"(r) : "f"(x));
    return r;
}
__device__ __forceinline__ float rtf(float x) { return __uint_as_float(f2tf(x)); }

__device__ __forceinline__ void mma8(float& d0, float& d1, float& d2, float& d3,
                                     uint32_t a0, uint32_t a1, uint32_t a2, uint32_t a3,
                                     uint32_t b0, uint32_t b1) {
    asm volatile(
        "mma.sync.aligned.m16n8k8.row.col.f32.tf32.tf32.f32 "
        "{%0,%1,%2,%3}, {%4,%5,%6,%7}, {%8,%9}, {%0,%1,%2,%3};"
        : "+f"(d0), "+f"(d1), "+f"(d2), "+f"(d3)
        : "r"(a0), "r"(a1), "r"(a2), "r"(a3), "r"(b0), "r"(b1));
}
__device__ __forceinline__ void ldsm4(uint32_t* r, uint32_t a) {
    asm volatile("ldmatrix.sync.aligned.m8n8.x4.shared.b16 {%0,%1,%2,%3}, [%4];"
                 : "=r"(r[0]), "=r"(r[1]), "=r"(r[2]), "=r"(r[3]) : "r"(a));
}
__device__ __forceinline__ void ldsm2(uint32_t* r, uint32_t a) {
    asm volatile("ldmatrix.sync.aligned.m8n8.x2.shared.b16 {%0,%1}, [%2];"
                 : "=r"(r[0]), "=r"(r[1]) : "r"(a));
}
__device__ __forceinline__ void cp16(void* dst, const void* src) {
    uint32_t d = (uint32_t)__cvta_generic_to_shared(dst);
    asm volatile("cp.async.cg.shared.global [%0], [%1], 16;" :: "r"(d), "l"(src));
}
__device__ __forceinline__ void cp4(void* dst, const void* src) {
    uint32_t d = (uint32_t)__cvta_generic_to_shared(dst);
    asm volatile("cp.async.ca.shared.global [%0], [%1], 4;" :: "r"(d), "l"(src));
}
__device__ __forceinline__ void cpcommit() { asm volatile("cp.async.commit_group;"); }
template<int NG> __device__ __forceinline__ void cpwait() {
    asm volatile("cp.async.wait_group %0;" :: "n"(NG));
}

// ---------------------------------------------------------------------------
// Fused prep: tf32-round all GEMM operands + A transform, one launch.
// ---------------------------------------------------------------------------
#define P_S0 ((size_t)(Tt * DIN / 4))                       // x
#define P_S1 (P_S0 + (size_t)(DM * DIN / 4))                // ip_w
#define P_S2 (P_S1 + (size_t)(NLr * 2 * EE * DM / 4))       // inproj_w
#define P_S3 (P_S2 + (size_t)(NLr * 96 * EE / 4))           // xproj_w
#define P_S4 (P_S3 + (size_t)(NLr * DM * EE / 4))           // outproj_w
#define P_S5 (P_S4 + (size_t)(DIN * DM / 4))                // op_w
#define P_TOT (P_S5 + (size_t)(NLr * EE * NN))              // + A elems

__global__ void prep_all(const float4* __restrict__ x,   const float4* __restrict__ ipw,
                         const float4* __restrict__ inw, const float4* __restrict__ xpw,
                         const float4* __restrict__ otw, const float4* __restrict__ opw,
                         const float* __restrict__ A_log)
{
    const size_t i = (size_t)blockIdx.x * 256 + threadIdx.x;
    if (i < P_S5) {
        const float4* s; float4* d; size_t j;
        if      (i < P_S0) { s = x;   d = (float4*)g_xr;       j = i; }
        else if (i < P_S1) { s = ipw; d = (float4*)g_wip;      j = i - P_S0; }
        else if (i < P_S2) { s = inw; d = (float4*)g_winproj;  j = i - P_S1; }
        else if (i < P_S3) { s = xpw; d = (float4*)g_wxproj;   j = i - P_S2; }
        else if (i < P_S4) { s = otw; d = (float4*)g_woutproj; j = i - P_S3; }
        else               { s = opw; d = (float4*)g_wop;      j = i - P_S4; }
        float4 v = s[j];
        v.x = rtf(v.x); v.y = rtf(v.y); v.z = rtf(v.z); v.w = rtf(v.w);
        d[j] = v;
    } else if (i < P_TOT) {
        const size_t j = i - P_S5;
        g_A[j] = -expf(A_log[j]);
    }
}

// ---------------------------------------------------------------------------
// TF32 HMMA GEMM (proven config): 3-stage cp.async + ldmatrix.
// SK: split-K over blockIdx.z; chunk length = K arg; C -> partials [z][M][N].
// ---------------------------------------------------------------------------
template<int WMW, int WNW, int BETA, int BIAS, int SK>
__global__ __launch_bounds__(WMW * WNW * 32, 2)
void tgemm(const float* __restrict__ A, const float* __restrict__ W,
           const float* __restrict__ bias, float* __restrict__ C,
           int M, int N, int K, int lda)
{
    constexpr int NT  = WMW * WNW * 32;
    constexpr int BM  = WMW * 64;
    constexpr int BN  = WNW * 32;
    constexpr int ST  = 3;
    constexpr int AW  = BM * 20;
    constexpr int BW  = BN * 20;
    constexpr int AIT = (BM * 4 + NT - 1) / NT;
    constexpr int BIT = (BN * 4 + NT - 1) / NT;

    extern __shared__ float dynsm[];

    if (SK) {
        A += (size_t)blockIdx.z * K;
        W += (size_t)blockIdx.z * K;
        C += (size_t)blockIdx.z * M * N;
    }

    const int tid  = threadIdx.x;
    const int bm   = blockIdx.y * BM;
    const int bn   = blockIdx.x * BN;
    const int wid  = tid >> 5;
    const int lane = tid & 31;
    const int wm   = wid % WMW;
    const int wn   = wid / WMW;
    const int l4   = lane >> 2;
    const int lr   = lane & 3;

    const float* Ag = A + (size_t)bm * lda;
    const float* Wg = W + (size_t)bn * lda;

    float acc[4][4][4];
#pragma unroll
    for (int i = 0; i < 4; i++)
#pragma unroll
        for (int j = 0; j < 4; j++)
#pragma unroll
            for (int k = 0; k < 4; k++) acc[i][j][k] = 0.f;

    auto load_stage = [&](int st, int kt) {
        float* As = dynsm + st * AW;
        float* Bs = dynsm + ST * AW + st * BW;
#pragma unroll
        for (int i = 0; i < AIT; i++) {
            const int f = tid + i * NT;
            if (f < BM * 4) {
                const int row = f >> 2, c = (f & 3) << 2;
                cp16(As + row * 20 + c, Ag + (size_t)row * lda + kt * 16 + c);
            }
        }
#pragma unroll
        for (int i = 0; i < BIT; i++) {
            const int f = tid + i * NT;
            if (f < BN * 4) {
                const int row = f >> 2, c = (f & 3) << 2;
                cp16(Bs + row * 20 + c, Wg + (size_t)row * lda + kt * 16 + c);
            }
        }
        cpcommit();
    };

    load_stage(0, 0);
    load_stage(1, 1);

    const int sub  = lane >> 3, tr = lane & 7;
    const int aoff = ((sub & 1) * 8 + tr) * 20 + (sub >> 1) * 4;
    const int l15  = lane & 15;
    const int boff = (l15 & 7) * 20 + (l15 >> 3) * 4;
    const uint32_t Au = (uint32_t)__cvta_generic_to_shared(dynsm);
    const uint32_t Bu = (uint32_t)__cvta_generic_to_shared(dynsm + ST * AW);

    const int nt = K >> 4;
    for (int kt = 0; kt < nt; kt++) {
        cpwait<1>();
        __syncthreads();
        if (kt + 2 < nt) load_stage((kt + 2) % ST, kt + 2);

        const int st = kt % ST;
        const uint32_t aB = Au + (uint32_t)(st * AW + wm * 64 * 20 + aoff) * 4;
        const uint32_t bB = Bu + (uint32_t)(st * BW + wn * 32 * 20 + boff) * 4;
#pragma unroll
        for (int ks = 0; ks < 2; ks++) {
            uint32_t af[4][4], bf[4][2];
#pragma unroll
            for (int mt = 0; mt < 4; mt++)
                ldsm4(af[mt], aB + (uint32_t)(mt * 16 * 20 + ks * 8) * 4);
#pragma unroll
            for (int ntt = 0; ntt < 4; ntt++)
                ldsm2(bf[ntt], bB + (uint32_t)(ntt * 8 * 20 + ks * 8) * 4);
#pragma unroll
            for (int mt = 0; mt < 4; mt++)
#pragma unroll
                for (int ntt = 0; ntt < 4; ntt++)
                    mma8(acc[mt][ntt][0], acc[mt][ntt][1], acc[mt][ntt][2], acc[mt][ntt][3],
                         af[mt][0], af[mt][1], af[mt][2], af[mt][3],
                         bf[ntt][0], bf[ntt][1]);
        }
    }

#pragma unroll
    for (int mt = 0; mt < 4; mt++) {
        const int r0 = bm + wm * 64 + mt * 16 + l4;
#pragma unroll
        for (int ntt = 0; ntt < 4; ntt++) {
            const int c0 = bn + wn * 32 + ntt * 8 + lr * 2;
            float* p0 = C + (size_t)r0 * N + c0;
            float* p1 = p0 + (size_t)8 * N;
            float v0 = acc[mt][ntt][0], v1 = acc[mt][ntt][1];
            float v2 = acc[mt][ntt][2], v3 = acc[mt][ntt][3];
            if (BIAS) {
                const float b0 = bias[c0], b1 = bias[c0 + 1];
                v0 += b0; v1 += b1; v2 += b0; v3 += b1;
            }
            if (BETA) {
                const float2 o0 = *(const float2*)p0;
                const float2 o1 = *(const float2*)p1;
                v0 += o0.x; v1 += o0.y; v2 += o1.x; v3 += o1.y;
            }
            *(float2*)p0 = make_float2(v0, v1);
            *(float2*)p1 = make_float2(v2, v3);
        }
    }
}

// ---------------------------------------------------------------------------
// xred: reduce ALL 96 xproj split-K columns once (z-order preserved).
// ---------------------------------------------------------------------------
__global__ void xred_kernel()
{
    const int i = blockIdx.x * 256 + threadIdx.x;   // Tt*96
    float s = 0.f;
#pragma unroll
    for (int z = 0; z < XSK; z++) s += g_xpart[(size_t)z * Tt * 96 + i];
    g_xdbl[i] = s;
}

// ---------------------------------------------------------------------------
// LayerNorm variants with fused split-K reduction of the residual stream.
// ---------------------------------------------------------------------------
__device__ __forceinline__ void ln_core(float4 v, const float* w, const float* b,
                                        float* o, int row, int tid,
                                        float* s1, float* s2)
{
    float s  = v.x + v.y + v.z + v.w;
    float ss = v.x * v.x + v.y * v.y + v.z * v.z + v.w * v.w;
#pragma unroll
    for (int off = 16; off; off >>= 1) {
        s  += __shfl_xor_sync(0xffffffffu, s,  off);
        ss += __shfl_xor_sync(0xffffffffu, ss, off);
    }
    if ((tid & 31) == 0) { s1[tid >> 5] = s; s2[tid >> 5] = ss; }
    __syncthreads();
    float ts = 0.f, tss = 0.f;
#pragma unroll
    for (int i = 0; i < 8; i++) { ts += s1[i]; tss += s2[i]; }
    const float mean = ts * (1.f / DM);
    const float var  = tss * (1.f / DM) - mean * mean;
    const float rstd = rsqrtf(var + 1e-5f);
    const float4 wv = ((const float4*)w)[tid];
    const float4 bv = ((const float4*)b)[tid];
    float4 r;
    r.x = rtf((v.x - mean) * rstd * wv.x + bv.x);
    r.y = rtf((v.y - mean) * rstd * wv.y + bv.y);
    r.z = rtf((v.z - mean) * rstd * wv.z + bv.z);
    r.w = rtf((v.w - mean) * rstd * wv.w + bv.w);
    ((float4*)(o + (size_t)row * DM))[tid] = r;
}

__global__ void ln0_kernel(const float* __restrict__ bias,
                           const float* __restrict__ w, const float* __restrict__ b)
{
    __shared__ float s1[8], s2[8];
    const int row = blockIdx.x;
    const int tid = threadIdx.x;
    const float4 p0 = ((const float4*)(g_gp + (size_t)row * DM))[tid];
    const float4 p1 = ((const float4*)(g_gp + (size_t)Tt * DM + (size_t)row * DM))[tid];
    const float4 bb = ((const float4*)bias)[tid];
    float4 v;
    v.x = p0.x + p1.x + bb.x; v.y = p0.y + p1.y + bb.y;
    v.z = p0.z + p1.z + bb.z; v.w = p0.w + p1.w + bb.w;
    ((float4*)(g_h + (size_t)row * DM))[tid] = v;
    ln_core(v, w, b, g_hn, row, tid, s1, s2);
}

__global__ void lnr_kernel(const float* __restrict__ w, const float* __restrict__ b)
{
    __shared__ float s1[8], s2[8];
    const int row = blockIdx.x;
    const int tid = threadIdx.x;
    const float4 hv = ((const float4*)(g_h + (size_t)row * DM))[tid];
    const float4 p0 = ((const float4*)(g_gp + (size_t)row * DM))[tid];
    const float4 p1 = ((const float4*)(g_gp + (size_t)Tt * DM + (size_t)row * DM))[tid];
    float4 v;
    v.x = hv.x + p0.x + p1.x; v.y = hv.y + p0.y + p1.y;
    v.z = hv.z + p0.z + p1.z; v.w = hv.w + p0.w + p1.w;
    ((float4*)(g_h + (size_t)row * DM))[tid] = v;
    ln_core(v, w, b, g_hn, row, tid, s1, s2);
}

// ---------------------------------------------------------------------------
// opred: out = sum_{z<4} gp[z] + op_b   (final projection split-K reduce)
// ---------------------------------------------------------------------------
__global__ void opred_kernel(const float4* __restrict__ opb, float4* __restrict__ out)
{
    const int i = blockIdx.x * 256 + threadIdx.x;   // Tt*DIN/4
    const float4* g = (const float4*)g_gp;
    const int P = Tt * DIN / 4;
    const float4 a = g[i], b4 = g[P + i], c = g[2 * P + i], d = g[3 * P + i];
    const float4 bb = opb[i & (DIN / 4 - 1)];
    float4 r;
    r.x = a.x + b4.x + c.x + d.x + bb.x;
    r.y = a.y + b4.y + c.y + d.y + bb.y;
    r.z = a.z + b4.z + c.z + d.z + bb.z;
    r.w = a.w + b4.w + c.w + d.w + bb.w;
    out[i] = r;
}

// ---------------------------------------------------------------------------
// Depthwise causal conv (K=4) + SiLU (output rounded to tf32)
// ---------------------------------------------------------------------------
__global__ void conv_kernel(const float* __restrict__ cw, const float* __restrict__ cb)
{
    const int idx = blockIdx.x * 256 + threadIdx.x;
    const int e  = idx & (EE - 1);
    const int bt = idx >> 11;
    const int t  = bt & (Ll - 1);
    float acc = cb[e];
    const float* base = g_xz + (size_t)bt * (2 * EE) + e;
#pragma unroll
    for (int k = 0; k < 4; k++) {
        const int tt = t - 3 + k;
        if (tt >= 0) acc += cw[e * 4 + k] * base[(size_t)(k - 3) * (2 * EE)];
    }
    g_xm[idx] = rtf(acc / (1.f + __expf(-acc)));
}

// ---------------------------------------------------------------------------
// dtproj GEMM + softplus (fp32); X read from reduced g_xdbl.
// ---------------------------------------------------------------------------
__global__ __launch_bounds__(256)
void dt_kernel(const float* __restrict__ W, const float* __restrict__ db)
{
    __shared__ float Xs[16][64];
    __shared__ float Wt[64][132];
    const int tid = threadIdx.x;
    const int bm = blockIdx.y * 16;
    const int bn = blockIdx.x * 128;
    {
        const int m  = tid >> 4;
        const int k4 = (tid & 15) << 2;
        *(float4*)&Xs[m][k4] = *(const float4*)(g_xdbl + (size_t)(bm + m) * 96 + k4);
    }
#pragma unroll
    for (int r = 0; r < 8; r++) {
        const int idx = tid + 256 * r;
        const int n  = idx >> 4;
        const int k4 = (idx & 15) << 2;
        float4 v = *(const float4*)(W + (size_t)(bn + n) * 64 + k4);
        Wt[k4 + 0][n] = v.x; Wt[k4 + 1][n] = v.y;
        Wt[k4 + 2][n] = v.z; Wt[k4 + 3][n] = v.w;
    }
    __syncthreads();

    const int nb = (tid & 31) << 2;
    const int m0 = tid >> 5;
    float acc[2][4];
#pragma unroll
    for (int i = 0; i < 2; i++)
#pragma unroll
        for (int j = 0; j < 4; j++) acc[i][j] = 0.f;
#pragma unroll
    for (int k = 0; k < 64; k++) {
        const float4 w = *(const float4*)&Wt[k][nb];
        const float x0 = Xs[m0][k];
        const float x1 = Xs[m0 + 8][k];
        acc[0][0] = fmaf(x0, w.x, acc[0][0]); acc[0][1] = fmaf(x0, w.y, acc[0][1]);
        acc[0][2] = fmaf(x0, w.z, acc[0][2]); acc[0][3] = fmaf(x0, w.w, acc[0][3]);
        acc[1][0] = fmaf(x1, w.x, acc[1][0]); acc[1][1] = fmaf(x1, w.y, acc[1][1]);
        acc[1][2] = fmaf(x1, w.z, acc[1][2]); acc[1][3] = fmaf(x1, w.w, acc[1][3]);
    }
#pragma unroll
    for (int i = 0; i < 2; i++) {
        const int row = bm + m0 + 8 * i;
#pragma unroll
        for (int j = 0; j < 4; j++) {
            float v = acc[i][j] + db[bn + nb + j];
            v = (v > 20.f) ? v : log1pf(expf(v));
            g_dt[(size_t)row * EE + bn + nb + j] = v;
        }
    }
}

// ---------------------------------------------------------------------------
// Selective scan: chunked smem staging + x4-unrolled shfl reductions.
// ---------------------------------------------------------------------------
#define CH 64
__global__ __launch_bounds__(128)
void scan_kernel(int layer, const float* __restrict__ Dl)
{
    __shared__ float s_dt[2][CH][8];
    __shared__ float s_u [2][CH][8];
    __shared__ float s_zg[2][CH][8];
    __shared__ float s_B [2][CH][16];
    __shared__ float s_C [2][CH][16];
    __shared__ float s_y [CH][8];

    const int b   = blockIdx.y;
    const int e0  = blockIdx.x * 8;
    const int tid = threadIdx.x;
    const int eg  = tid >> 4;
    const int n   = tid & 15;

    const float Av = g_A[(size_t)layer * EE * NN + (e0 + eg) * NN + n];
    const float Dv = Dl[e0 + eg];

    auto load_chunk = [&](int buf, int t0) {
        const size_t bt0 = (size_t)(b * Ll + t0);
#pragma unroll
        for (int it = 0; it < 4; it++) {
            const int idx = tid + it * 128;
            const int t = idx >> 3, e = idx & 7;
            cp4(&s_dt[buf][t][e], &g_dt[(bt0 + t) * EE + e0 + e]);
            cp4(&s_u [buf][t][e], &g_xm[(bt0 + t) * EE + e0 + e]);
            cp4(&s_zg[buf][t][e], &g_xz[(bt0 + t) * (2 * EE) + EE + e0 + e]);
        }
#pragma unroll
        for (int it = 0; it < 8; it++) {
            const int idx = tid + it * 128;
            const int t = idx >> 4, nn = idx & 15;
            cp4(&s_B[buf][t][nn], &g_xdbl[(bt0 + t) * 96 + 64 + nn]);
            cp4(&s_C[buf][t][nn], &g_xdbl[(bt0 + t) * 96 + 80 + nn]);
        }
        cpcommit();
    };

    load_chunk(0, 0);

    float h = 0.f;
    const int NC = Ll / CH;
    for (int c = 0; c < NC; c++) {
        const int buf = c & 1;
        if (c + 1 < NC) { load_chunk(buf ^ 1, (c + 1) * CH); cpwait<1>(); }
        else            { cpwait<0>(); }
        __syncthreads();

#pragma unroll 4
        for (int tb = 0; tb < CH; tb += 4) {
            float p[4];
#pragma unroll
            for (int j = 0; j < 4; j++) {
                const float dt = s_dt[buf][tb + j][eg];
                const float uu = s_u [buf][tb + j][eg];
                const float Bv = s_B [buf][tb + j][n];
                const float Cv = s_C [buf][tb + j][n];
                const float dA = __expf(dt * Av);
                h = fmaf(dA, h, dt * uu * Bv);
                p[j] = h * Cv;
            }
#pragma unroll
            for (int off = 8; off; off >>= 1)
#pragma unroll
                for (int j = 0; j < 4; j++)
                    p[j] += __shfl_xor_sync(0xffffffffu, p[j], off);
            if (n == 0) {
#pragma unroll
                for (int j = 0; j < 4; j++) {
                    const float uu = s_u [buf][tb + j][eg];
                    const float zg = s_zg[buf][tb + j][eg];
                    const float sil = zg / (1.f + __expf(-zg));
                    s_y[tb + j][eg] = (p[j] + uu * Dv) * sil;
                }
            }
        }
        __syncthreads();

        const size_t bt0 = (size_t)(b * Ll + c * CH);
#pragma unroll
        for (int it = 0; it < 4; it++) {
            const int idx = tid + it * 128;
            const int t = idx >> 3, e = idx & 7;
            g_y[(bt0 + t) * EE + e0 + e] = rtf(s_y[t][e]);
        }
    }
}

// ---------------------------------------------------------------------------
extern "C" void kernel_launch(void* const* d_in, const int* in_sizes, int n_in,
                              void* d_out, int out_size)
{
    const float* x         = (const float*)d_in[0];
    const float* ip_w      = (const float*)d_in[2];
    const float* ip_b      = (const float*)d_in[3];
    const float* ln_w      = (const float*)d_in[4];
    const float* ln_b      = (const float*)d_in[5];
    const float* inproj_w  = (const float*)d_in[6];
    const float* conv_w    = (const float*)d_in[7];
    const float* conv_b    = (const float*)d_in[8];
    const float* xproj_w   = (const float*)d_in[9];
    const float* dtproj_w  = (const float*)d_in[10];
    const float* dtproj_b  = (const float*)d_in[11];
    const float* A_log     = (const float*)d_in[12];
    const float* Dp        = (const float*)d_in[13];
    const float* outproj_w = (const float*)d_in[14];
    const float* fnorm_w   = (const float*)d_in[15];
    const float* fnorm_b   = (const float*)d_in[16];
    const float* op_w      = (const float*)d_in[17];
    const float* op_b      = (const float*)d_in[18];
    float* out = (float*)d_out;

    float *p_hn, *p_xm, *p_y, *p_xr, *p_xpart, *p_gp, *p_xz;
    float *p_wip, *p_winproj, *p_wxproj, *p_woutproj, *p_wop;
    cudaGetSymbolAddress((void**)&p_hn,       g_hn);
    cudaGetSymbolAddress((void**)&p_xm,       g_xm);
    cudaGetSymbolAddress((void**)&p_y,        g_y);
    cudaGetSymbolAddress((void**)&p_xr,       g_xr);
    cudaGetSymbolAddress((void**)&p_xpart,    g_xpart);
    cudaGetSymbolAddress((void**)&p_gp,       g_gp);
    cudaGetSymbolAddress((void**)&p_xz,       g_xz);
    cudaGetSymbolAddress((void**)&p_wip,      g_wip);
    cudaGetSymbolAddress((void**)&p_winproj,  g_winproj);
    cudaGetSymbolAddress((void**)&p_wxproj,   g_wxproj);
    cudaGetSymbolAddress((void**)&p_woutproj, g_woutproj);
    cudaGetSymbolAddress((void**)&p_wop,      g_wop);

    const int SM4 = 3 * (128 * 20 + 128 * 20) * 4;
    const int SM3 = 3 * (128 * 20 +  96 * 20) * 4;
    cudaFuncSetAttribute(tgemm<2,4,0,0,0>, cudaFuncAttributeMaxDynamicSharedMemorySize, SM4);
    cudaFuncSetAttribute(tgemm<2,4,0,0,1>, cudaFuncAttributeMaxDynamicSharedMemorySize, SM4);
    cudaFuncSetAttribute(tgemm<2,3,0,0,1>, cudaFuncAttributeMaxDynamicSharedMemorySize, SM3);

    // (1) fused prep
    {
        const int nblk = (int)((P_TOT + 255) / 256);
        prep_all<<<nblk, 256>>>((const float4*)x, (const float4*)ip_w,
                                (const float4*)inproj_w, (const float4*)xproj_w,
                                (const float4*)outproj_w, (const float4*)op_w, A_log);
    }

    // (2) ip GEMM split-K=2 -> partials (bias added in ln0)
    tgemm<2,4,0,0,1><<<dim3(DM / 128, Tt / 128, 2), 256, SM4>>>(
        p_xr, p_wip, nullptr, p_gp, Tt, DM, DIN / 2, DIN);

    for (int l = 0; l < NLr; l++) {
        // (3) fused residual-reduce + layernorm
        if (l == 0)
            ln0_kernel<<<Tt, 256>>>(ip_b, ln_w, ln_b);
        else
            lnr_kernel<<<Tt, 256>>>(ln_w + (size_t)l * DM, ln_b + (size_t)l * DM);

        // (4) xz = hn @ inproj_w^T   [T, 4096]   <- profiled slot on l=0
        tgemm<2,4,0,0,0><<<dim3((2 * EE) / 128, Tt / 128), 256, SM4>>>(
            p_hn, p_winproj + (size_t)l * 2 * EE * DM, nullptr, p_xz, Tt, 2 * EE, DM, DM);

        conv_kernel<<<(Tt * EE) / 256, 256>>>(conv_w + (size_t)l * EE * 4,
                                              conv_b + (size_t)l * EE);

        // x_dbl partials = xm @ xproj_w^T  (split-K = 16 -> 256 blocks)
        tgemm<2,3,0,0,1><<<dim3(1, Tt / 128, XSK), 192, SM3>>>(
            p_xm, p_wxproj + (size_t)l * 96 * EE, nullptr, p_xpart,
            Tt, 96, EE / XSK, EE);

        // reduce ALL 96 columns once (cheap; avoids per-bn re-reduction in dt)
        xred_kernel<<<(Tt * 96) / 256, 256>>>();

        dt_kernel<<<dim3(EE / 128, Tt / 16), 256>>>(dtproj_w + (size_t)l * EE * RR,
                                                    dtproj_b + (size_t)l * EE);

        scan_kernel<<<dim3(EE / 8, Bb), 128>>>(l, Dp + (size_t)l * EE);

        // outproj split-K=2 -> partials (residual add fused into next lnr)
        tgemm<2,4,0,0,1><<<dim3(DM / 128, Tt / 128, 2), 256, SM4>>>(
            p_y, p_woutproj + (size_t)l * DM * EE, nullptr, p_gp, Tt, DM, EE / 2, EE);
    }

    // final: h += last outproj partials; hn = LN(h)
    lnr_kernel<<<Tt, 256>>>(fnorm_w, fnorm_b);

    // out = hn @ op_w^T + op_b : split-K=4 -> partials, then reduce+bias
    tgemm<2,4,0,0,1><<<dim3(DIN / 128, Tt / 128, 4), 256, SM4>>>(
        p_hn, p_wop, nullptr, p_gp, Tt, DIN, DM / 4, DM);
    opred_kernel<<<(Tt * DIN / 4) / 256, 256>>>((const float4*)op_b, (float4*)out);
}

// round 16
// speedup vs baseline: 1.6830x; 1.0144x over previous
#include <cuda_runtime.h>
#include <math.h>
#include <stdint.h>

// Problem constants
#define Bb   2
#define Ll   1024
#define Tt   2048        // Bb*Ll tokens
#define DIN  512
#define DM   1024
#define NLr  4
#define EE   2048
#define NN   16
#define RR   64
#define XSK  16          // split-K factor for xproj

// ---------------- scratch (device globals; no runtime allocation) ----------
__device__ float g_h   [Tt * DM];
__device__ float g_hn  [Tt * DM];
__device__ float g_xz  [Tt * 2 * EE];
__device__ float g_xm  [Tt * EE];
__device__ float g_xdbl[Tt * 96];
__device__ float g_dt  [Tt * EE];
__device__ float g_y   [Tt * EE];
__device__ float g_A   [NLr * EE * NN];
__device__ float g_xr  [Tt * DIN];                 // tf32-rounded x
__device__ float g_xpart[XSK * Tt * 96];           // xproj split-K partials
__device__ float g_gp  [4 * Tt * DIN];             // generic split-K partials
// tf32-rounded weights
__device__ float g_wip     [DM * DIN];
__device__ float g_winproj [NLr * 2 * EE * DM];
__device__ float g_wxproj  [NLr * 96 * EE];
__device__ float g_woutproj[NLr * DM * EE];
__device__ float g_wop     [DIN * DM];

// ---------------------------------------------------------------------------
// helpers
// ---------------------------------------------------------------------------
__device__ __forceinline__ uint32_t f2tf(float x) {
    uint32_t r;
    asm("cvt.rna.tf32.f32 %0, %1;" : "=r"(r) : "f"(x));
    return r;
}
__device__ __forceinline__ float rtf(float x) { return __uint_as_float(f2tf(x)); }

__device__ __forceinline__ void mma8(float& d0, float& d1, float& d2, float& d3,
                                     uint32_t a0, uint32_t a1, uint32_t a2, uint32_t a3,
                                     uint32_t b0, uint32_t b1) {
    asm volatile(
        "mma.sync.aligned.m16n8k8.row.col.f32.tf32.tf32.f32 "
        "{%0,%1,%2,%3}, {%4,%5,%6,%7}, {%8,%9}, {%0,%1,%2,%3};"
        : "+f"(d0), "+f"(d1), "+f"(d2), "+f"(d3)
        : "r"(a0), "r"(a1), "r"(a2), "r"(a3), "r"(b0), "r"(b1));
}
__device__ __forceinline__ void ldsm4(uint32_t* r, uint32_t a) {
    asm volatile("ldmatrix.sync.aligned.m8n8.x4.shared.b16 {%0,%1,%2,%3}, [%4];"
                 : "=r"(r[0]), "=r"(r[1]), "=r"(r[2]), "=r"(r[3]) : "r"(a));
}
__device__ __forceinline__ void ldsm2(uint32_t* r, uint32_t a) {
    asm volatile("ldmatrix.sync.aligned.m8n8.x2.shared.b16 {%0,%1}, [%2];"
                 : "=r"(r[0]), "=r"(r[1]) : "r"(a));
}
__device__ __forceinline__ void cp16(void* dst, const void* src) {
    uint32_t d = (uint32_t)__cvta_generic_to_shared(dst);
    asm volatile("cp.async.cg.shared.global [%0], [%1], 16;" :: "r"(d), "l"(src));
}
__device__ __forceinline__ void cp4(void* dst, const void* src) {
    uint32_t d = (uint32_t)__cvta_generic_to_shared(dst);
    asm volatile("cp.async.ca.shared.global [%0], [%1], 4;" :: "r"(d), "l"(src));
}
__device__ __forceinline__ void cpcommit() { asm volatile("cp.async.commit_group;"); }
template<int NG> __device__ __forceinline__ void cpwait() {
    asm volatile("cp.async.wait_group %0;" :: "n"(NG));
}

// ---------------------------------------------------------------------------
// Fused prep: tf32-round all GEMM operands + A transform, one launch.
// ---------------------------------------------------------------------------
#define P_S0 ((size_t)(Tt * DIN / 4))                       // x
#define P_S1 (P_S0 + (size_t)(DM * DIN / 4))                // ip_w
#define P_S2 (P_S1 + (size_t)(NLr * 2 * EE * DM / 4))       // inproj_w
#define P_S3 (P_S2 + (size_t)(NLr * 96 * EE / 4))           // xproj_w
#define P_S4 (P_S3 + (size_t)(NLr * DM * EE / 4))           // outproj_w
#define P_S5 (P_S4 + (size_t)(DIN * DM / 4))                // op_w
#define P_TOT (P_S5 + (size_t)(NLr * EE * NN))              // + A elems

__global__ void prep_all(const float4* __restrict__ x,   const float4* __restrict__ ipw,
                         const float4* __restrict__ inw, const float4* __restrict__ xpw,
                         const float4* __restrict__ otw, const float4* __restrict__ opw,
                         const float* __restrict__ A_log)
{
    const size_t i = (size_t)blockIdx.x * 256 + threadIdx.x;
    if (i < P_S5) {
        const float4* s; float4* d; size_t j;
        if      (i < P_S0) { s = x;   d = (float4*)g_xr;       j = i; }
        else if (i < P_S1) { s = ipw; d = (float4*)g_wip;      j = i - P_S0; }
        else if (i < P_S2) { s = inw; d = (float4*)g_winproj;  j = i - P_S1; }
        else if (i < P_S3) { s = xpw; d = (float4*)g_wxproj;   j = i - P_S2; }
        else if (i < P_S4) { s = otw; d = (float4*)g_woutproj; j = i - P_S3; }
        else               { s = opw; d = (float4*)g_wop;      j = i - P_S4; }
        float4 v = s[j];
        v.x = rtf(v.x); v.y = rtf(v.y); v.z = rtf(v.z); v.w = rtf(v.w);
        d[j] = v;
    } else if (i < P_TOT) {
        const size_t j = i - P_S5;
        g_A[j] = -expf(A_log[j]);
    }
}

// ---------------------------------------------------------------------------
// TF32 HMMA GEMM: 3-stage cp.async + ldmatrix, one barrier per k-tile.
//   Big-GEMM config now <2,2>: 128 threads, BM=128, BN=64 -> 4 independent
//   blocks/SM (decoupled barrier groups to overlap LDSM/MMA phases).
//   xproj config <2,3>: 192 threads, split-K.
// SK: split-K over blockIdx.z; chunk length = K arg; C -> partials [z][M][N].
// ---------------------------------------------------------------------------
template<int WMW, int WNW, int BETA, int BIAS, int SK>
__global__ __launch_bounds__(WMW * WNW * 32, 2)
void tgemm(const float* __restrict__ A, const float* __restrict__ W,
           const float* __restrict__ bias, float* __restrict__ C,
           int M, int N, int K, int lda)
{
    constexpr int NT  = WMW * WNW * 32;
    constexpr int BM  = WMW * 64;
    constexpr int BN  = WNW * 32;
    constexpr int ST  = 3;
    constexpr int AW  = BM * 20;
    constexpr int BW  = BN * 20;
    constexpr int AIT = (BM * 4 + NT - 1) / NT;
    constexpr int BIT = (BN * 4 + NT - 1) / NT;

    extern __shared__ float dynsm[];

    if (SK) {
        A += (size_t)blockIdx.z * K;
        W += (size_t)blockIdx.z * K;
        C += (size_t)blockIdx.z * M * N;
    }

    const int tid  = threadIdx.x;
    const int bm   = blockIdx.y * BM;
    const int bn   = blockIdx.x * BN;
    const int wid  = tid >> 5;
    const int lane = tid & 31;
    const int wm   = wid % WMW;
    const int wn   = wid / WMW;
    const int l4   = lane >> 2;
    const int lr   = lane & 3;

    const float* Ag = A + (size_t)bm * lda;
    const float* Wg = W + (size_t)bn * lda;

    float acc[4][4][4];
#pragma unroll
    for (int i = 0; i < 4; i++)
#pragma unroll
        for (int j = 0; j < 4; j++)
#pragma unroll
            for (int k = 0; k < 4; k++) acc[i][j][k] = 0.f;

    auto load_stage = [&](int st, int kt) {
        float* As = dynsm + st * AW;
        float* Bs = dynsm + ST * AW + st * BW;
#pragma unroll
        for (int i = 0; i < AIT; i++) {
            const int f = tid + i * NT;
            if (f < BM * 4) {
                const int row = f >> 2, c = (f & 3) << 2;
                cp16(As + row * 20 + c, Ag + (size_t)row * lda + kt * 16 + c);
            }
        }
#pragma unroll
        for (int i = 0; i < BIT; i++) {
            const int f = tid + i * NT;
            if (f < BN * 4) {
                const int row = f >> 2, c = (f & 3) << 2;
                cp16(Bs + row * 20 + c, Wg + (size_t)row * lda + kt * 16 + c);
            }
        }
        cpcommit();
    };

    load_stage(0, 0);
    load_stage(1, 1);

    const int sub  = lane >> 3, tr = lane & 7;
    const int aoff = ((sub & 1) * 8 + tr) * 20 + (sub >> 1) * 4;
    const int l15  = lane & 15;
    const int boff = (l15 & 7) * 20 + (l15 >> 3) * 4;
    const uint32_t Au = (uint32_t)__cvta_generic_to_shared(dynsm);
    const uint32_t Bu = (uint32_t)__cvta_generic_to_shared(dynsm + ST * AW);

    const int nt = K >> 4;
    for (int kt = 0; kt < nt; kt++) {
        cpwait<1>();
        __syncthreads();
        if (kt + 2 < nt) load_stage((kt + 2) % ST, kt + 2);

        const int st = kt % ST;
        const uint32_t aB = Au + (uint32_t)(st * AW + wm * 64 * 20 + aoff) * 4;
        const uint32_t bB = Bu + (uint32_t)(st * BW + wn * 32 * 20 + boff) * 4;
#pragma unroll
        for (int ks = 0; ks < 2; ks++) {
            uint32_t af[4][4], bf[4][2];
#pragma unroll
            for (int mt = 0; mt < 4; mt++)
                ldsm4(af[mt], aB + (uint32_t)(mt * 16 * 20 + ks * 8) * 4);
#pragma unroll
            for (int ntt = 0; ntt < 4; ntt++)
                ldsm2(bf[ntt], bB + (uint32_t)(ntt * 8 * 20 + ks * 8) * 4);
#pragma unroll
            for (int mt = 0; mt < 4; mt++)
#pragma unroll
                for (int ntt = 0; ntt < 4; ntt++)
                    mma8(acc[mt][ntt][0], acc[mt][ntt][1], acc[mt][ntt][2], acc[mt][ntt][3],
                         af[mt][0], af[mt][1], af[mt][2], af[mt][3],
                         bf[ntt][0], bf[ntt][1]);
        }
    }

#pragma unroll
    for (int mt = 0; mt < 4; mt++) {
        const int r0 = bm + wm * 64 + mt * 16 + l4;
#pragma unroll
        for (int ntt = 0; ntt < 4; ntt++) {
            const int c0 = bn + wn * 32 + ntt * 8 + lr * 2;
            float* p0 = C + (size_t)r0 * N + c0;
            float* p1 = p0 + (size_t)8 * N;
            float v0 = acc[mt][ntt][0], v1 = acc[mt][ntt][1];
            float v2 = acc[mt][ntt][2], v3 = acc[mt][ntt][3];
            if (BIAS) {
                const float b0 = bias[c0], b1 = bias[c0 + 1];
                v0 += b0; v1 += b1; v2 += b0; v3 += b1;
            }
            if (BETA) {
                const float2 o0 = *(const float2*)p0;
                const float2 o1 = *(const float2*)p1;
                v0 += o0.x; v1 += o0.y; v2 += o1.x; v3 += o1.y;
            }
            *(float2*)p0 = make_float2(v0, v1);
            *(float2*)p1 = make_float2(v2, v3);
        }
    }
}

// ---------------------------------------------------------------------------
// xred: reduce ALL 96 xproj split-K columns once (z-order preserved).
// ---------------------------------------------------------------------------
__global__ void xred_kernel()
{
    const int i = blockIdx.x * 256 + threadIdx.x;   // Tt*96
    float s = 0.f;
#pragma unroll
    for (int z = 0; z < XSK; z++) s += g_xpart[(size_t)z * Tt * 96 + i];
    g_xdbl[i] = s;
}

// ---------------------------------------------------------------------------
// LayerNorm variants with fused split-K reduction of the residual stream.
// ---------------------------------------------------------------------------
__device__ __forceinline__ void ln_core(float4 v, const float* w, const float* b,
                                        float* o, int row, int tid,
                                        float* s1, float* s2)
{
    float s  = v.x + v.y + v.z + v.w;
    float ss = v.x * v.x + v.y * v.y + v.z * v.z + v.w * v.w;
#pragma unroll
    for (int off = 16; off; off >>= 1) {
        s  += __shfl_xor_sync(0xffffffffu, s,  off);
        ss += __shfl_xor_sync(0xffffffffu, ss, off);
    }
    if ((tid & 31) == 0) { s1[tid >> 5] = s; s2[tid >> 5] = ss; }
    __syncthreads();
    float ts = 0.f, tss = 0.f;
#pragma unroll
    for (int i = 0; i < 8; i++) { ts += s1[i]; tss += s2[i]; }
    const float mean = ts * (1.f / DM);
    const float var  = tss * (1.f / DM) - mean * mean;
    const float rstd = rsqrtf(var + 1e-5f);
    const float4 wv = ((const float4*)w)[tid];
    const float4 bv = ((const float4*)b)[tid];
    float4 r;
    r.x = rtf((v.x - mean) * rstd * wv.x + bv.x);
    r.y = rtf((v.y - mean) * rstd * wv.y + bv.y);
    r.z = rtf((v.z - mean) * rstd * wv.z + bv.z);
    r.w = rtf((v.w - mean) * rstd * wv.w + bv.w);
    ((float4*)(o + (size_t)row * DM))[tid] = r;
}

__global__ void ln0_kernel(const float* __restrict__ bias,
                           const float* __restrict__ w, const float* __restrict__ b)
{
    __shared__ float s1[8], s2[8];
    const int row = blockIdx.x;
    const int tid = threadIdx.x;
    const float4 p0 = ((const float4*)(g_gp + (size_t)row * DM))[tid];
    const float4 p1 = ((const float4*)(g_gp + (size_t)Tt * DM + (size_t)row * DM))[tid];
    const float4 bb = ((const float4*)bias)[tid];
    float4 v;
    v.x = p0.x + p1.x + bb.x; v.y = p0.y + p1.y + bb.y;
    v.z = p0.z + p1.z + bb.z; v.w = p0.w + p1.w + bb.w;
    ((float4*)(g_h + (size_t)row * DM))[tid] = v;
    ln_core(v, w, b, g_hn, row, tid, s1, s2);
}

__global__ void lnr_kernel(const float* __restrict__ w, const float* __restrict__ b)
{
    __shared__ float s1[8], s2[8];
    const int row = blockIdx.x;
    const int tid = threadIdx.x;
    const float4 hv = ((const float4*)(g_h + (size_t)row * DM))[tid];
    const float4 p0 = ((const float4*)(g_gp + (size_t)row * DM))[tid];
    const float4 p1 = ((const float4*)(g_gp + (size_t)Tt * DM + (size_t)row * DM))[tid];
    float4 v;
    v.x = hv.x + p0.x + p1.x; v.y = hv.y + p0.y + p1.y;
    v.z = hv.z + p0.z + p1.z; v.w = hv.w + p0.w + p1.w;
    ((float4*)(g_h + (size_t)row * DM))[tid] = v;
    ln_core(v, w, b, g_hn, row, tid, s1, s2);
}

// ---------------------------------------------------------------------------
// opred: out = sum_{z<4} gp[z] + op_b   (final projection split-K reduce)
// ---------------------------------------------------------------------------
__global__ void opred_kernel(const float4* __restrict__ opb, float4* __restrict__ out)
{
    const int i = blockIdx.x * 256 + threadIdx.x;   // Tt*DIN/4
    const float4* g = (const float4*)g_gp;
    const int P = Tt * DIN / 4;
    const float4 a = g[i], b4 = g[P + i], c = g[2 * P + i], d = g[3 * P + i];
    const float4 bb = opb[i & (DIN / 4 - 1)];
    float4 r;
    r.x = a.x + b4.x + c.x + d.x + bb.x;
    r.y = a.y + b4.y + c.y + d.y + bb.y;
    r.z = a.z + b4.z + c.z + d.z + bb.z;
    r.w = a.w + b4.w + c.w + d.w + bb.w;
    out[i] = r;
}

// ---------------------------------------------------------------------------
// Depthwise causal conv (K=4) + SiLU (output rounded to tf32)
// ---------------------------------------------------------------------------
__global__ void conv_kernel(const float* __restrict__ cw, const float* __restrict__ cb)
{
    const int idx = blockIdx.x * 256 + threadIdx.x;
    const int e  = idx & (EE - 1);
    const int bt = idx >> 11;
    const int t  = bt & (Ll - 1);
    float acc = cb[e];
    const float* base = g_xz + (size_t)bt * (2 * EE) + e;
#pragma unroll
    for (int k = 0; k < 4; k++) {
        const int tt = t - 3 + k;
        if (tt >= 0) acc += cw[e * 4 + k] * base[(size_t)(k - 3) * (2 * EE)];
    }
    g_xm[idx] = rtf(acc / (1.f + __expf(-acc)));
}

// ---------------------------------------------------------------------------
// dtproj GEMM + softplus (fp32); X read from reduced g_xdbl.
// ---------------------------------------------------------------------------
__global__ __launch_bounds__(256)
void dt_kernel(const float* __restrict__ W, const float* __restrict__ db)
{
    __shared__ float Xs[16][64];
    __shared__ float Wt[64][132];
    const int tid = threadIdx.x;
    const int bm = blockIdx.y * 16;
    const int bn = blockIdx.x * 128;
    {
        const int m  = tid >> 4;
        const int k4 = (tid & 15) << 2;
        *(float4*)&Xs[m][k4] = *(const float4*)(g_xdbl + (size_t)(bm + m) * 96 + k4);
    }
#pragma unroll
    for (int r = 0; r < 8; r++) {
        const int idx = tid + 256 * r;
        const int n  = idx >> 4;
        const int k4 = (idx & 15) << 2;
        float4 v = *(const float4*)(W + (size_t)(bn + n) * 64 + k4);
        Wt[k4 + 0][n] = v.x; Wt[k4 + 1][n] = v.y;
        Wt[k4 + 2][n] = v.z; Wt[k4 + 3][n] = v.w;
    }
    __syncthreads();

    const int nb = (tid & 31) << 2;
    const int m0 = tid >> 5;
    float acc[2][4];
#pragma unroll
    for (int i = 0; i < 2; i++)
#pragma unroll
        for (int j = 0; j < 4; j++) acc[i][j] = 0.f;
#pragma unroll
    for (int k = 0; k < 64; k++) {
        const float4 w = *(const float4*)&Wt[k][nb];
        const float x0 = Xs[m0][k];
        const float x1 = Xs[m0 + 8][k];
        acc[0][0] = fmaf(x0, w.x, acc[0][0]); acc[0][1] = fmaf(x0, w.y, acc[0][1]);
        acc[0][2] = fmaf(x0, w.z, acc[0][2]); acc[0][3] = fmaf(x0, w.w, acc[0][3]);
        acc[1][0] = fmaf(x1, w.x, acc[1][0]); acc[1][1] = fmaf(x1, w.y, acc[1][1]);
        acc[1][2] = fmaf(x1, w.z, acc[1][2]); acc[1][3] = fmaf(x1, w.w, acc[1][3]);
    }
#pragma unroll
    for (int i = 0; i < 2; i++) {
        const int row = bm + m0 + 8 * i;
#pragma unroll
        for (int j = 0; j < 4; j++) {
            float v = acc[i][j] + db[bn + nb + j];
            v = (v > 20.f) ? v : log1pf(expf(v));
            g_dt[(size_t)row * EE + bn + nb + j] = v;
        }
    }
}

// ---------------------------------------------------------------------------
// Selective scan: chunked smem staging + x4-unrolled shfl reductions.
// ---------------------------------------------------------------------------
#define CH 64
__global__ __launch_bounds__(128)
void scan_kernel(int layer, const float* __restrict__ Dl)
{
    __shared__ float s_dt[2][CH][8];
    __shared__ float s_u [2][CH][8];
    __shared__ float s_zg[2][CH][8];
    __shared__ float s_B [2][CH][16];
    __shared__ float s_C [2][CH][16];
    __shared__ float s_y [CH][8];

    const int b   = blockIdx.y;
    const int e0  = blockIdx.x * 8;
    const int tid = threadIdx.x;
    const int eg  = tid >> 4;
    const int n   = tid & 15;

    const float Av = g_A[(size_t)layer * EE * NN + (e0 + eg) * NN + n];
    const float Dv = Dl[e0 + eg];

    auto load_chunk = [&](int buf, int t0) {
        const size_t bt0 = (size_t)(b * Ll + t0);
#pragma unroll
        for (int it = 0; it < 4; it++) {
            const int idx = tid + it * 128;
            const int t = idx >> 3, e = idx & 7;
            cp4(&s_dt[buf][t][e], &g_dt[(bt0 + t) * EE + e0 + e]);
            cp4(&s_u [buf][t][e], &g_xm[(bt0 + t) * EE + e0 + e]);
            cp4(&s_zg[buf][t][e], &g_xz[(bt0 + t) * (2 * EE) + EE + e0 + e]);
        }
#pragma unroll
        for (int it = 0; it < 8; it++) {
            const int idx = tid + it * 128;
            const int t = idx >> 4, nn = idx & 15;
            cp4(&s_B[buf][t][nn], &g_xdbl[(bt0 + t) * 96 + 64 + nn]);
            cp4(&s_C[buf][t][nn], &g_xdbl[(bt0 + t) * 96 + 80 + nn]);
        }
        cpcommit();
    };

    load_chunk(0, 0);

    float h = 0.f;
    const int NC = Ll / CH;
    for (int c = 0; c < NC; c++) {
        const int buf = c & 1;
        if (c + 1 < NC) { load_chunk(buf ^ 1, (c + 1) * CH); cpwait<1>(); }
        else            { cpwait<0>(); }
        __syncthreads();

#pragma unroll 4
        for (int tb = 0; tb < CH; tb += 4) {
            float p[4];
#pragma unroll
            for (int j = 0; j < 4; j++) {
                const float dt = s_dt[buf][tb + j][eg];
                const float uu = s_u [buf][tb + j][eg];
                const float Bv = s_B [buf][tb + j][n];
                const float Cv = s_C [buf][tb + j][n];
                const float dA = __expf(dt * Av);
                h = fmaf(dA, h, dt * uu * Bv);
                p[j] = h * Cv;
            }
#pragma unroll
            for (int off = 8; off; off >>= 1)
#pragma unroll
                for (int j = 0; j < 4; j++)
                    p[j] += __shfl_xor_sync(0xffffffffu, p[j], off);
            if (n == 0) {
#pragma unroll
                for (int j = 0; j < 4; j++) {
                    const float uu = s_u [buf][tb + j][eg];
                    const float zg = s_zg[buf][tb + j][eg];
                    const float sil = zg / (1.f + __expf(-zg));
                    s_y[tb + j][eg] = (p[j] + uu * Dv) * sil;
                }
            }
        }
        __syncthreads();

        const size_t bt0 = (size_t)(b * Ll + c * CH);
#pragma unroll
        for (int it = 0; it < 4; it++) {
            const int idx = tid + it * 128;
            const int t = idx >> 3, e = idx & 7;
            g_y[(bt0 + t) * EE + e0 + e] = rtf(s_y[t][e]);
        }
    }
}

// ---------------------------------------------------------------------------
extern "C" void kernel_launch(void* const* d_in, const int* in_sizes, int n_in,
                              void* d_out, int out_size)
{
    const float* x         = (const float*)d_in[0];
    const float* ip_w      = (const float*)d_in[2];
    const float* ip_b      = (const float*)d_in[3];
    const float* ln_w      = (const float*)d_in[4];
    const float* ln_b      = (const float*)d_in[5];
    const float* inproj_w  = (const float*)d_in[6];
    const float* conv_w    = (const float*)d_in[7];
    const float* conv_b    = (const float*)d_in[8];
    const float* xproj_w   = (const float*)d_in[9];
    const float* dtproj_w  = (const float*)d_in[10];
    const float* dtproj_b  = (const float*)d_in[11];
    const float* A_log     = (const float*)d_in[12];
    const float* Dp        = (const float*)d_in[13];
    const float* outproj_w = (const float*)d_in[14];
    const float* fnorm_w   = (const float*)d_in[15];
    const float* fnorm_b   = (const float*)d_in[16];
    const float* op_w      = (const float*)d_in[17];
    const float* op_b      = (const float*)d_in[18];
    float* out = (float*)d_out;

    float *p_hn, *p_xm, *p_y, *p_xr, *p_xpart, *p_gp, *p_xz;
    float *p_wip, *p_winproj, *p_wxproj, *p_woutproj, *p_wop;
    cudaGetSymbolAddress((void**)&p_hn,       g_hn);
    cudaGetSymbolAddress((void**)&p_xm,       g_xm);
    cudaGetSymbolAddress((void**)&p_y,        g_y);
    cudaGetSymbolAddress((void**)&p_xr,       g_xr);
    cudaGetSymbolAddress((void**)&p_xpart,    g_xpart);
    cudaGetSymbolAddress((void**)&p_gp,       g_gp);
    cudaGetSymbolAddress((void**)&p_xz,       g_xz);
    cudaGetSymbolAddress((void**)&p_wip,      g_wip);
    cudaGetSymbolAddress((void**)&p_winproj,  g_winproj);
    cudaGetSymbolAddress((void**)&p_wxproj,   g_wxproj);
    cudaGetSymbolAddress((void**)&p_woutproj, g_woutproj);
    cudaGetSymbolAddress((void**)&p_wop,      g_wop);

    // smem sizes: <2,2> big config 3*(128+64)*20*4 = 46080 B; xproj <2,3> 53760 B
    const int SM22 = 3 * (128 * 20 +  64 * 20) * 4;
    const int SM3  = 3 * (128 * 20 +  96 * 20) * 4;
    cudaFuncSetAttribute(tgemm<2,2,0,0,0>, cudaFuncAttributeMaxDynamicSharedMemorySize, SM22);
    cudaFuncSetAttribute(tgemm<2,2,0,0,1>, cudaFuncAttributeMaxDynamicSharedMemorySize, SM22);
    cudaFuncSetAttribute(tgemm<2,3,0,0,1>, cudaFuncAttributeMaxDynamicSharedMemorySize, SM3);

    // (1) fused prep
    {
        const int nblk = (int)((P_TOT + 255) / 256);
        prep_all<<<nblk, 256>>>((const float4*)x, (const float4*)ip_w,
                                (const float4*)inproj_w, (const float4*)xproj_w,
                                (const float4*)outproj_w, (const float4*)op_w, A_log);
    }

    // (2) ip GEMM split-K=2 -> partials (bias added in ln0)
    tgemm<2,2,0,0,1><<<dim3(DM / 64, Tt / 128, 2), 128, SM22>>>(
        p_xr, p_wip, nullptr, p_gp, Tt, DM, DIN / 2, DIN);

    for (int l = 0; l < NLr; l++) {
        // (3) fused residual-reduce + layernorm
        if (l == 0)
            ln0_kernel<<<Tt, 256>>>(ip_b, ln_w, ln_b);
        else
            lnr_kernel<<<Tt, 256>>>(ln_w + (size_t)l * DM, ln_b + (size_t)l * DM);

        // (4) xz = hn @ inproj_w^T   [T, 4096]   <- profiled slot on l=0
        tgemm<2,2,0,0,0><<<dim3((2 * EE) / 64, Tt / 128), 128, SM22>>>(
            p_hn, p_winproj + (size_t)l * 2 * EE * DM, nullptr, p_xz, Tt, 2 * EE, DM, DM);

        conv_kernel<<<(Tt * EE) / 256, 256>>>(conv_w + (size_t)l * EE * 4,
                                              conv_b + (size_t)l * EE);

        // x_dbl partials = xm @ xproj_w^T  (split-K = 16 -> 256 blocks)
        tgemm<2,3,0,0,1><<<dim3(1, Tt / 128, XSK), 192, SM3>>>(
            p_xm, p_wxproj + (size_t)l * 96 * EE, nullptr, p_xpart,
            Tt, 96, EE / XSK, EE);

        xred_kernel<<<(Tt * 96) / 256, 256>>>();

        dt_kernel<<<dim3(EE / 128, Tt / 16), 256>>>(dtproj_w + (size_t)l * EE * RR,
                                                    dtproj_b + (size_t)l * EE);

        scan_kernel<<<dim3(EE / 8, Bb), 128>>>(l, Dp + (size_t)l * EE);

        // outproj split-K=2 -> partials (residual add fused into next lnr)
        tgemm<2,2,0,0,1><<<dim3(DM / 64, Tt / 128, 2), 128, SM22>>>(
            p_y, p_woutproj + (size_t)l * DM * EE, nullptr, p_gp, Tt, DM, EE / 2, EE);
    }

    // final: h += last outproj partials; hn = LN(h)
    lnr_kernel<<<Tt, 256>>>(fnorm_w, fnorm_b);

    // out = hn @ op_w^T + op_b : split-K=4 -> partials, then reduce+bias
    tgemm<2,2,0,0,1><<<dim3(DIN / 64, Tt / 128, 4), 128, SM22>>>(
        p_hn, p_wop, nullptr, p_gp, Tt, DIN, DM / 4, DM);
    opred_kernel<<<(Tt * DIN / 4) / 256, 256>>>((const float4*)op_b, (float4*)out);
}